// round 2
// baseline (speedup 1.0000x reference)
#include <cuda_runtime.h>
#include <cstdint>

#define NN   10000
#define PP   4
#define EE   160000
#define INF_ 256
#define HH   8
#define DD   64
#define HD_  512
#define NEG_SLOPE 0.2f

// ---------------- device scratch (no allocs allowed) ----------------
__device__ float g_Wh[(size_t)PP * NN * HD_];   // per-path transformed features
__device__ float g_z [(size_t)PP * NN * HD_];   // per-path aggregated output (accumulator -> elu'd emb)
__device__ float g_el[(size_t)PP * NN * HH];
__device__ float g_er[(size_t)PP * NN * HH];
__device__ float g_ex[(size_t)PP * EE * HH];
__device__ float g_s [(size_t)PP * NN * HH];
__device__ float g_w [PP];
__device__ float g_beta[PP];

// ---------------- K0: zero accumulators ----------------
__global__ void k_zero() {
    size_t i = (size_t)blockIdx.x * blockDim.x + threadIdx.x;
    size_t stride = (size_t)gridDim.x * blockDim.x;
    size_t nz4 = (size_t)PP * NN * HD_ / 4;
    float4 z4 = make_float4(0.f, 0.f, 0.f, 0.f);
    float4* z = (float4*)g_z;
    for (size_t j = i; j < nz4; j += stride) z[j] = z4;
    size_t ns = (size_t)PP * NN * HH;
    for (size_t j = i; j < ns; j += stride) g_s[j] = 0.f;
    if (i < PP) g_w[i] = 0.f;
}

// ---------------- K1: Wh = h @ W[p]   (fp32 tiled GEMM) ----------------
// grid: (ceil(N/64), HD/64, P), block: 256
__global__ void k_gemm(const float* __restrict__ h, const float* __restrict__ W) {
    __shared__ float As[16][65];
    __shared__ float Bs[16][64];
    int p  = blockIdx.z;
    int m0 = blockIdx.x * 64;
    int n0 = blockIdx.y * 64;
    const float* B = W + (size_t)p * INF_ * HD_;
    int t  = threadIdx.x;
    int tr = (t >> 4) * 4;      // 0..60
    int tc = (t & 15) * 4;      // 0..60
    float acc[4][4] = {};
    for (int k0 = 0; k0 < INF_; k0 += 16) {
        #pragma unroll
        for (int i = t; i < 64 * 16; i += 256) {
            int m = i >> 4, k = i & 15;
            int gm = m0 + m;
            As[k][m] = (gm < NN) ? h[(size_t)gm * INF_ + k0 + k] : 0.f;
        }
        #pragma unroll
        for (int i = t; i < 16 * 64; i += 256) {
            int k = i >> 6, n = i & 63;
            Bs[k][n] = B[(size_t)(k0 + k) * HD_ + n0 + n];
        }
        __syncthreads();
        #pragma unroll
        for (int k = 0; k < 16; k++) {
            float a[4], b[4];
            #pragma unroll
            for (int i = 0; i < 4; i++) a[i] = As[k][tr + i];
            #pragma unroll
            for (int j = 0; j < 4; j++) b[j] = Bs[k][tc + j];
            #pragma unroll
            for (int i = 0; i < 4; i++)
                #pragma unroll
                for (int j = 0; j < 4; j++) acc[i][j] += a[i] * b[j];
        }
        __syncthreads();
    }
    #pragma unroll
    for (int i = 0; i < 4; i++) {
        int gm = m0 + tr + i;
        if (gm < NN) {
            float4 v = make_float4(acc[i][0], acc[i][1], acc[i][2], acc[i][3]);
            *(float4*)&g_Wh[((size_t)p * NN + gm) * HD_ + n0 + tc] = v;
        }
    }
}

// ---------------- K2: el/er = sum_d Wh * attn ----------------
// one warp per (p, n). grid: P*N/8 blocks of 256
__global__ void k_attn(const float* __restrict__ al, const float* __restrict__ ar) {
    int w    = (blockIdx.x * blockDim.x + threadIdx.x) >> 5;
    int lane = threadIdx.x & 31;
    int p = w / NN, n = w % NN;
    int head = lane >> 2;
    const float4* wh  = (const float4*)&g_Wh[((size_t)p * NN + n) * HD_ + lane * 16];
    const float4* a4l = (const float4*)&al[(p * HH + head) * DD + (lane & 3) * 16];
    const float4* a4r = (const float4*)&ar[(p * HH + head) * DD + (lane & 3) * 16];
    float sl = 0.f, sr = 0.f;
    #pragma unroll
    for (int q = 0; q < 4; q++) {
        float4 x = wh[q], l = a4l[q], r = a4r[q];
        sl += x.x * l.x + x.y * l.y + x.z * l.z + x.w * l.w;
        sr += x.x * r.x + x.y * r.y + x.z * r.z + x.w * r.w;
    }
    sl += __shfl_xor_sync(~0u, sl, 1); sl += __shfl_xor_sync(~0u, sl, 2);
    sr += __shfl_xor_sync(~0u, sr, 1); sr += __shfl_xor_sync(~0u, sr, 2);
    if ((lane & 3) == 0) {
        g_el[((size_t)p * NN + n) * HH + head] = sl;
        g_er[((size_t)p * NN + n) * HH + head] = sr;
    }
}

// ---------------- K3: edge pass A: ex = exp(leakyrelu(el[src]+er[dst])), s[dst] += ex ----
// grid: (E/256, P)
__global__ void k_edgeA(const int* __restrict__ esrc, const int* __restrict__ edst) {
    int e = blockIdx.x * blockDim.x + threadIdx.x;
    int p = blockIdx.y;
    int s = esrc[(size_t)p * EE + e];
    int d = edst[(size_t)p * EE + e];
    const float* el = &g_el[((size_t)p * NN + s) * HH];
    const float* er = &g_er[((size_t)p * NN + d) * HH];
    float*       ex = &g_ex[((size_t)p * EE + e) * HH];
    float*       sp = &g_s [((size_t)p * NN + d) * HH];
    #pragma unroll
    for (int h = 0; h < HH; h++) {
        float v = el[h] + er[h];
        v = v > 0.f ? v : NEG_SLOPE * v;
        float xv = expf(v);         // shift-free softmax: exp won't overflow here
        ex[h] = xv;
        atomicAdd(&sp[h], xv);
    }
}

// ---------------- K4: edge pass B: z[dst] += alpha * Wh[src] ----------------
// one warp per (p, edge). grid: (E/8, P), block 256
__global__ void k_edgeB(const int* __restrict__ esrc, const int* __restrict__ edst) {
    int lane = threadIdx.x & 31;
    int e = blockIdx.x * 8 + (threadIdx.x >> 5);
    int p = blockIdx.y;
    int s = esrc[(size_t)p * EE + e];
    int d = edst[(size_t)p * EE + e];
    int head = lane >> 2;
    float alpha = g_ex[((size_t)p * EE + e) * HH + head] /
                  g_s [((size_t)p * NN + d) * HH + head];
    const float4* src4 = (const float4*)&g_Wh[((size_t)p * NN + s) * HD_ + lane * 16];
    float* dst = &g_z[((size_t)p * NN + d) * HD_ + lane * 16];
    #pragma unroll
    for (int q = 0; q < 4; q++) {
        float4 v = src4[q];
        asm volatile("red.global.add.v4.f32 [%0], {%1,%2,%3,%4};"
                     :: "l"(dst + q * 4),
                        "f"(v.x * alpha), "f"(v.y * alpha),
                        "f"(v.z * alpha), "f"(v.w * alpha)
                     : "memory");
    }
}

// ---------------- K5: elu(z + b), then semantic partial: w[p] += tanh(z@W1+b1)@W2 ----
// grid: (N/8, P), block 256.  smem: 16KB zs + 16KB w1s + 1KB red = 33KB
__global__ void k_post(const float* __restrict__ gb, const float* __restrict__ W1,
                       const float* __restrict__ b1, const float* __restrict__ W2) {
    __shared__ float zs[8 * HD_];    // 16 KB
    __shared__ float w1s[64 * 64];   // 16 KB
    __shared__ float red[256];
    int p  = blockIdx.y;
    int n0 = blockIdx.x * 8;
    int t  = threadIdx.x;
    // phase 1: bias + elu, write back, cache in smem
    for (int i = t; i < 8 * HD_; i += 256) {
        int node = i >> 9, c = i & 511;
        size_t gi = ((size_t)p * NN + n0 + node) * HD_ + c;
        float v = g_z[gi] + gb[p * HD_ + c];
        v = v > 0.f ? v : expm1f(v);
        g_z[gi] = v;
        zs[i]   = v;
    }
    __syncthreads();
    // phase 2: hidden = zs @ W1  (8 nodes x 64 hidden), k-chunked
    int j = t & 63, grp = t >> 6;            // 2 nodes per thread (4 groups)
    float acc0 = 0.f, acc1 = 0.f;
    for (int kc = 0; kc < 8; kc++) {
        for (int i = t; i < 64 * 64; i += 256)
            w1s[i] = W1[(size_t)(kc * 64 + (i >> 6)) * 64 + (i & 63)];
        __syncthreads();
        #pragma unroll
        for (int k = 0; k < 64; k++) {
            float w1 = w1s[k * 64 + j];
            int zb = kc * 64 + k;
            acc0 += zs[(grp * 2 + 0) * HD_ + zb] * w1;
            acc1 += zs[(grp * 2 + 1) * HD_ + zb] * w1;
        }
        __syncthreads();
    }
    float b = b1[j], w2 = W2[j];
    float contrib = tanhf(acc0 + b) * w2 + tanhf(acc1 + b) * w2;
    red[t] = contrib;
    __syncthreads();
    for (int ofs = 128; ofs > 0; ofs >>= 1) {
        if (t < ofs) red[t] += red[t + ofs];
        __syncthreads();
    }
    if (t == 0) atomicAdd(&g_w[p], red[0]);
}

// ---------------- K6: beta = softmax(w / N) ----------------
__global__ void k_beta() {
    if (threadIdx.x == 0) {
        float w[PP], m = -1e30f;
        #pragma unroll
        for (int p = 0; p < PP; p++) { w[p] = g_w[p] / (float)NN; m = fmaxf(m, w[p]); }
        float s = 0.f;
        #pragma unroll
        for (int p = 0; p < PP; p++) { w[p] = expf(w[p] - m); s += w[p]; }
        #pragma unroll
        for (int p = 0; p < PP; p++) g_beta[p] = w[p] / s;
    }
}

// ---------------- K7: out = sum_p beta[p] * z[p] ----------------
__global__ void k_comb(float* __restrict__ out) {
    int i = blockIdx.x * blockDim.x + threadIdx.x;   // float4 index, N*HD/4 total
    const float4* z = (const float4*)g_z;
    const size_t stride = (size_t)NN * HD_ / 4;
    float b0 = g_beta[0], b1 = g_beta[1], b2 = g_beta[2], b3 = g_beta[3];
    float4 a = z[i];
    float4 b = z[i + stride];
    float4 c = z[i + 2 * stride];
    float4 d = z[i + 3 * stride];
    float4 o;
    o.x = b0 * a.x + b1 * b.x + b2 * c.x + b3 * d.x;
    o.y = b0 * a.y + b1 * b.y + b2 * c.y + b3 * d.y;
    o.z = b0 * a.z + b1 * b.z + b2 * c.z + b3 * d.z;
    o.w = b0 * a.w + b1 * b.w + b2 * c.w + b3 * d.w;
    ((float4*)out)[i] = o;
}

// ---------------- launcher ----------------
extern "C" void kernel_launch(void* const* d_in, const int* in_sizes, int n_in,
                              void* d_out, int out_size) {
    const float* h     = (const float*)d_in[0];
    const int*   esrc  = (const int*)  d_in[1];
    const int*   edst  = (const int*)  d_in[2];
    const float* gat_W = (const float*)d_in[3];
    const float* al    = (const float*)d_in[4];
    const float* ar    = (const float*)d_in[5];
    const float* gat_b = (const float*)d_in[6];
    const float* sW1   = (const float*)d_in[7];
    const float* sb1   = (const float*)d_in[8];
    const float* sW2   = (const float*)d_in[9];
    float* out = (float*)d_out;

    k_zero<<<2048, 256>>>();

    dim3 gg((NN + 63) / 64, HD_ / 64, PP);
    k_gemm<<<gg, 256>>>(h, gat_W);

    k_attn<<<(PP * NN) / 8, 256>>>(al, ar);

    dim3 ga(EE / 256, PP);
    k_edgeA<<<ga, 256>>>(esrc, edst);

    dim3 gb(EE / 8, PP);
    k_edgeB<<<gb, 256>>>(esrc, edst);

    dim3 gp(NN / 8, PP);
    k_post<<<gp, 256>>>(gat_b, sW1, sb1, sW2);

    k_beta<<<1, 32>>>();

    k_comb<<<(NN * HD_ / 4) / 256, 256>>>(out);
}

// round 3
// speedup vs baseline: 1.1691x; 1.1691x over previous
#include <cuda_runtime.h>
#include <cstdint>

#define NN   10000
#define PP   4
#define EE   160000
#define INF_ 256
#define HH   8
#define DD   64
#define HD_  512
#define NEG_SLOPE 0.2f

// ---------------- device scratch (no allocs allowed) ----------------
__device__ float g_Wh[(size_t)PP * NN * HD_];
__device__ float g_z [(size_t)PP * NN * HD_];
__device__ float g_el[(size_t)PP * NN * HH];
__device__ float g_er[(size_t)PP * NN * HH];
__device__ float g_ex[(size_t)PP * EE * HH];
__device__ float g_s [(size_t)PP * NN * HH];
__device__ float g_w [PP];
__device__ float g_beta[PP];

// ---------------- K0: zero accumulators ----------------
__global__ void k_zero() {
    size_t i = (size_t)blockIdx.x * blockDim.x + threadIdx.x;
    size_t stride = (size_t)gridDim.x * blockDim.x;
    size_t nz4 = (size_t)PP * NN * HD_ / 4;
    float4 z4 = make_float4(0.f, 0.f, 0.f, 0.f);
    float4* z = (float4*)g_z;
    for (size_t j = i; j < nz4; j += stride) z[j] = z4;
    size_t ns = (size_t)PP * NN * HH;
    for (size_t j = i; j < ns; j += stride) g_s[j] = 0.f;
    if (i < PP) g_w[i] = 0.f;
}

// ---------------- tf32 helpers ----------------
__device__ __forceinline__ uint32_t f2tf32(float x) {
    uint32_t r;
    asm("cvt.rna.tf32.f32 %0, %1;" : "=r"(r) : "f"(x));
    return r;
}

__device__ __forceinline__ void mma_tf32(float& c0, float& c1, float& c2, float& c3,
                                         uint32_t a0, uint32_t a1, uint32_t a2, uint32_t a3,
                                         uint32_t b0, uint32_t b1) {
    asm volatile("mma.sync.aligned.m16n8k8.row.col.f32.tf32.tf32.f32 "
                 "{%0,%1,%2,%3}, {%4,%5,%6,%7}, {%8,%9}, {%0,%1,%2,%3};"
                 : "+f"(c0), "+f"(c1), "+f"(c2), "+f"(c3)
                 : "r"(a0), "r"(a1), "r"(a2), "r"(a3), "r"(b0), "r"(b1));
}

// ---------------- K1: Wh = h @ W[p]  (tf32 tensor-core, hi/lo split for fp32 accuracy) ----
// BM=64, BN=128, BK=16. 256 threads = 8 warps, warp tile 32x32.
// grid: (ceil(N/64), HD/128=4, P)
__global__ __launch_bounds__(256) void k_gemm(const float* __restrict__ h,
                                              const float* __restrict__ W) {
    __shared__ uint32_t As_hi[64][17];
    __shared__ uint32_t As_lo[64][17];
    __shared__ uint32_t Bs_hi[16][132];
    __shared__ uint32_t Bs_lo[16][132];

    int p  = blockIdx.z;
    int m0 = blockIdx.x * 64;
    int n0 = blockIdx.y * 128;
    const float* B = W + (size_t)p * INF_ * HD_;
    int t    = threadIdx.x;
    int lane = t & 31;
    int w    = t >> 5;
    int warp_m = (w & 1) * 32;    // 0 or 32
    int warp_n = (w >> 1) * 32;   // 0..96
    int g   = lane >> 2;          // 0..7
    int tid = lane & 3;           // 0..3

    float acc[2][4][4];
    #pragma unroll
    for (int mt = 0; mt < 2; mt++)
        #pragma unroll
        for (int nt = 0; nt < 4; nt++)
            #pragma unroll
            for (int q = 0; q < 4; q++) acc[mt][nt][q] = 0.f;

    // A load indices: one float4 per thread
    int a_row = t >> 2;          // 0..63
    int a_k4  = (t & 3) * 4;     // 0,4,8,12
    int gm_a  = m0 + a_row;
    const bool a_ok = gm_a < NN;

    for (int kk0 = 0; kk0 < INF_; kk0 += 16) {
        // ---- load A tile (64x16), split hi/lo ----
        float4 va = a_ok ? *(const float4*)&h[(size_t)gm_a * INF_ + kk0 + a_k4]
                         : make_float4(0.f, 0.f, 0.f, 0.f);
        {
            float vv[4] = {va.x, va.y, va.z, va.w};
            #pragma unroll
            for (int j = 0; j < 4; j++) {
                uint32_t hb = f2tf32(vv[j]);
                As_hi[a_row][a_k4 + j] = hb;
                As_lo[a_row][a_k4 + j] = f2tf32(vv[j] - __uint_as_float(hb));
            }
        }
        // ---- load B tile (16x128), split hi/lo ----
        #pragma unroll
        for (int i = 0; i < 2; i++) {
            int idx = t + i * 256;
            int bk  = idx >> 5;            // 0..15
            int bn4 = (idx & 31) * 4;      // 0..124
            float4 vb = *(const float4*)&B[(size_t)(kk0 + bk) * HD_ + n0 + bn4];
            float vv[4] = {vb.x, vb.y, vb.z, vb.w};
            #pragma unroll
            for (int j = 0; j < 4; j++) {
                uint32_t hb = f2tf32(vv[j]);
                Bs_hi[bk][bn4 + j] = hb;
                Bs_lo[bk][bn4 + j] = f2tf32(vv[j] - __uint_as_float(hb));
            }
        }
        __syncthreads();

        #pragma unroll
        for (int ks = 0; ks < 16; ks += 8) {
            uint32_t ah[2][4], alo[2][4];
            #pragma unroll
            for (int mt = 0; mt < 2; mt++) {
                int r0 = warp_m + mt * 16;
                ah[mt][0]  = As_hi[r0 + g    ][ks + tid];
                ah[mt][1]  = As_hi[r0 + g + 8][ks + tid];
                ah[mt][2]  = As_hi[r0 + g    ][ks + tid + 4];
                ah[mt][3]  = As_hi[r0 + g + 8][ks + tid + 4];
                alo[mt][0] = As_lo[r0 + g    ][ks + tid];
                alo[mt][1] = As_lo[r0 + g + 8][ks + tid];
                alo[mt][2] = As_lo[r0 + g    ][ks + tid + 4];
                alo[mt][3] = As_lo[r0 + g + 8][ks + tid + 4];
            }
            uint32_t bh[4][2], blo[4][2];
            #pragma unroll
            for (int nt = 0; nt < 4; nt++) {
                int c0 = warp_n + nt * 8 + g;
                bh[nt][0]  = Bs_hi[ks + tid    ][c0];
                bh[nt][1]  = Bs_hi[ks + tid + 4][c0];
                blo[nt][0] = Bs_lo[ks + tid    ][c0];
                blo[nt][1] = Bs_lo[ks + tid + 4][c0];
            }
            #pragma unroll
            for (int mt = 0; mt < 2; mt++)
                #pragma unroll
                for (int nt = 0; nt < 4; nt++) {
                    float* c = acc[mt][nt];
                    mma_tf32(c[0], c[1], c[2], c[3],
                             ah[mt][0], ah[mt][1], ah[mt][2], ah[mt][3],
                             bh[nt][0], bh[nt][1]);
                    mma_tf32(c[0], c[1], c[2], c[3],
                             ah[mt][0], ah[mt][1], ah[mt][2], ah[mt][3],
                             blo[nt][0], blo[nt][1]);
                    mma_tf32(c[0], c[1], c[2], c[3],
                             alo[mt][0], alo[mt][1], alo[mt][2], alo[mt][3],
                             bh[nt][0], bh[nt][1]);
                }
        }
        __syncthreads();
    }

    // ---- epilogue ----
    #pragma unroll
    for (int mt = 0; mt < 2; mt++) {
        int r0 = m0 + warp_m + mt * 16 + g;
        int r1 = r0 + 8;
        #pragma unroll
        for (int nt = 0; nt < 4; nt++) {
            int c = n0 + warp_n + nt * 8 + tid * 2;
            if (r0 < NN)
                *(float2*)&g_Wh[((size_t)p * NN + r0) * HD_ + c] =
                    make_float2(acc[mt][nt][0], acc[mt][nt][1]);
            if (r1 < NN)
                *(float2*)&g_Wh[((size_t)p * NN + r1) * HD_ + c] =
                    make_float2(acc[mt][nt][2], acc[mt][nt][3]);
        }
    }
}

// ---------------- K2: el/er = sum_d Wh * attn ----------------
__global__ void k_attn(const float* __restrict__ al, const float* __restrict__ ar) {
    int w    = (blockIdx.x * blockDim.x + threadIdx.x) >> 5;
    int lane = threadIdx.x & 31;
    int p = w / NN, n = w % NN;
    int head = lane >> 2;
    const float4* wh  = (const float4*)&g_Wh[((size_t)p * NN + n) * HD_ + lane * 16];
    const float4* a4l = (const float4*)&al[(p * HH + head) * DD + (lane & 3) * 16];
    const float4* a4r = (const float4*)&ar[(p * HH + head) * DD + (lane & 3) * 16];
    float sl = 0.f, sr = 0.f;
    #pragma unroll
    for (int q = 0; q < 4; q++) {
        float4 x = wh[q], l = a4l[q], r = a4r[q];
        sl += x.x * l.x + x.y * l.y + x.z * l.z + x.w * l.w;
        sr += x.x * r.x + x.y * r.y + x.z * r.z + x.w * r.w;
    }
    sl += __shfl_xor_sync(~0u, sl, 1); sl += __shfl_xor_sync(~0u, sl, 2);
    sr += __shfl_xor_sync(~0u, sr, 1); sr += __shfl_xor_sync(~0u, sr, 2);
    if ((lane & 3) == 0) {
        g_el[((size_t)p * NN + n) * HH + head] = sl;
        g_er[((size_t)p * NN + n) * HH + head] = sr;
    }
}

// ---------------- K3: edge pass A (vectorized) ----------------
__global__ void k_edgeA(const int* __restrict__ esrc, const int* __restrict__ edst) {
    int e = blockIdx.x * blockDim.x + threadIdx.x;
    int p = blockIdx.y;
    int s = esrc[(size_t)p * EE + e];
    int d = edst[(size_t)p * EE + e];
    const float4* el4 = (const float4*)&g_el[((size_t)p * NN + s) * HH];
    const float4* er4 = (const float4*)&g_er[((size_t)p * NN + d) * HH];
    float4*       ex4 = (float4*)&g_ex[((size_t)p * EE + e) * HH];
    float*        sp  = &g_s [((size_t)p * NN + d) * HH];
    #pragma unroll
    for (int q = 0; q < 2; q++) {
        float4 l = el4[q], r = er4[q];
        float v[4] = {l.x + r.x, l.y + r.y, l.z + r.z, l.w + r.w};
        float x[4];
        #pragma unroll
        for (int j = 0; j < 4; j++) {
            float vv = v[j] > 0.f ? v[j] : NEG_SLOPE * v[j];
            x[j] = expf(vv);              // shift-free softmax (no overflow risk here)
        }
        ex4[q] = make_float4(x[0], x[1], x[2], x[3]);
        asm volatile("red.global.add.v4.f32 [%0], {%1,%2,%3,%4};"
                     :: "l"(sp + q * 4), "f"(x[0]), "f"(x[1]), "f"(x[2]), "f"(x[3])
                     : "memory");
    }
}

// ---------------- K4: edge pass B: z[dst] += alpha * Wh[src] ----------------
__global__ void k_edgeB(const int* __restrict__ esrc, const int* __restrict__ edst) {
    int lane = threadIdx.x & 31;
    int e = blockIdx.x * 8 + (threadIdx.x >> 5);
    int p = blockIdx.y;
    int s = esrc[(size_t)p * EE + e];
    int d = edst[(size_t)p * EE + e];
    int head = lane >> 2;
    float alpha = g_ex[((size_t)p * EE + e) * HH + head] /
                  g_s [((size_t)p * NN + d) * HH + head];
    const float4* src4 = (const float4*)&g_Wh[((size_t)p * NN + s) * HD_ + lane * 16];
    float* dst = &g_z[((size_t)p * NN + d) * HD_ + lane * 16];
    #pragma unroll
    for (int q = 0; q < 4; q++) {
        float4 v = src4[q];
        asm volatile("red.global.add.v4.f32 [%0], {%1,%2,%3,%4};"
                     :: "l"(dst + q * 4),
                        "f"(v.x * alpha), "f"(v.y * alpha),
                        "f"(v.z * alpha), "f"(v.w * alpha)
                     : "memory");
    }
}

// ---------------- K5: elu(z + b), then semantic partial ----------------
__global__ void k_post(const float* __restrict__ gb, const float* __restrict__ W1,
                       const float* __restrict__ b1, const float* __restrict__ W2) {
    __shared__ float zs[8 * HD_];
    __shared__ float w1s[64 * 64];
    __shared__ float red[256];
    int p  = blockIdx.y;
    int n0 = blockIdx.x * 8;
    int t  = threadIdx.x;
    for (int i = t; i < 8 * HD_; i += 256) {
        int node = i >> 9, c = i & 511;
        size_t gi = ((size_t)p * NN + n0 + node) * HD_ + c;
        float v = g_z[gi] + gb[p * HD_ + c];
        v = v > 0.f ? v : expm1f(v);
        g_z[gi] = v;
        zs[i]   = v;
    }
    __syncthreads();
    int j = t & 63, grp = t >> 6;
    float acc0 = 0.f, acc1 = 0.f;
    for (int kc = 0; kc < 8; kc++) {
        for (int i = t; i < 64 * 64; i += 256)
            w1s[i] = W1[(size_t)(kc * 64 + (i >> 6)) * 64 + (i & 63)];
        __syncthreads();
        #pragma unroll
        for (int k = 0; k < 64; k++) {
            float w1 = w1s[k * 64 + j];
            int zb = kc * 64 + k;
            acc0 += zs[(grp * 2 + 0) * HD_ + zb] * w1;
            acc1 += zs[(grp * 2 + 1) * HD_ + zb] * w1;
        }
        __syncthreads();
    }
    float b = b1[j], w2 = W2[j];
    float contrib = tanhf(acc0 + b) * w2 + tanhf(acc1 + b) * w2;
    red[t] = contrib;
    __syncthreads();
    for (int ofs = 128; ofs > 0; ofs >>= 1) {
        if (t < ofs) red[t] += red[t + ofs];
        __syncthreads();
    }
    if (t == 0) atomicAdd(&g_w[p], red[0]);
}

// ---------------- K6: beta = softmax(w / N) ----------------
__global__ void k_beta() {
    if (threadIdx.x == 0) {
        float w[PP], m = -1e30f;
        #pragma unroll
        for (int p = 0; p < PP; p++) { w[p] = g_w[p] / (float)NN; m = fmaxf(m, w[p]); }
        float s = 0.f;
        #pragma unroll
        for (int p = 0; p < PP; p++) { w[p] = expf(w[p] - m); s += w[p]; }
        #pragma unroll
        for (int p = 0; p < PP; p++) g_beta[p] = w[p] / s;
    }
}

// ---------------- K7: out = sum_p beta[p] * z[p] ----------------
__global__ void k_comb(float* __restrict__ out) {
    int i = blockIdx.x * blockDim.x + threadIdx.x;
    const float4* z = (const float4*)g_z;
    const size_t stride = (size_t)NN * HD_ / 4;
    float b0 = g_beta[0], b1 = g_beta[1], b2 = g_beta[2], b3 = g_beta[3];
    float4 a = z[i];
    float4 b = z[i + stride];
    float4 c = z[i + 2 * stride];
    float4 d = z[i + 3 * stride];
    float4 o;
    o.x = b0 * a.x + b1 * b.x + b2 * c.x + b3 * d.x;
    o.y = b0 * a.y + b1 * b.y + b2 * c.y + b3 * d.y;
    o.z = b0 * a.z + b1 * b.z + b2 * c.z + b3 * d.z;
    o.w = b0 * a.w + b1 * b.w + b2 * c.w + b3 * d.w;
    ((float4*)out)[i] = o;
}

// ---------------- launcher ----------------
extern "C" void kernel_launch(void* const* d_in, const int* in_sizes, int n_in,
                              void* d_out, int out_size) {
    const float* h     = (const float*)d_in[0];
    const int*   esrc  = (const int*)  d_in[1];
    const int*   edst  = (const int*)  d_in[2];
    const float* gat_W = (const float*)d_in[3];
    const float* al    = (const float*)d_in[4];
    const float* ar    = (const float*)d_in[5];
    const float* gat_b = (const float*)d_in[6];
    const float* sW1   = (const float*)d_in[7];
    const float* sb1   = (const float*)d_in[8];
    const float* sW2   = (const float*)d_in[9];
    float* out = (float*)d_out;

    k_zero<<<2048, 256>>>();

    dim3 gg((NN + 63) / 64, HD_ / 128, PP);
    k_gemm<<<gg, 256>>>(h, gat_W);

    k_attn<<<(PP * NN) / 8, 256>>>(al, ar);

    dim3 ga(EE / 256, PP);
    k_edgeA<<<ga, 256>>>(esrc, edst);

    dim3 gb(EE / 8, PP);
    k_edgeB<<<gb, 256>>>(esrc, edst);

    dim3 gp(NN / 8, PP);
    k_post<<<gp, 256>>>(gat_b, sW1, sb1, sW2);

    k_beta<<<1, 32>>>();

    k_comb<<<(NN * HD_ / 4) / 256, 256>>>(out);
}

// round 4
// speedup vs baseline: 1.4799x; 1.2658x over previous
#include <cuda_runtime.h>
#include <cstdint>

#define NN   10000
#define PP   4
#define EE   160000
#define INF_ 256
#define HH   8
#define DD   64
#define HD_  512
#define NEG_SLOPE 0.2f

// ---------------- device scratch ----------------
__device__ float g_Wh[(size_t)PP * NN * HD_];
__device__ float g_z [(size_t)PP * NN * HD_];
__device__ float g_el[(size_t)PP * NN * HH];
__device__ float g_er[(size_t)PP * NN * HH];
__device__ float g_ex[(size_t)PP * EE * HH];
__device__ int   g_cnt[PP * NN];
__device__ int   g_off[PP * NN];
__device__ int   g_pos[PP * NN];
__device__ int   g_eid[(size_t)PP * EE];
__device__ float g_w [PP];
__device__ float g_beta[PP];

// ---------------- K0: zero counters ----------------
__global__ void k_zero() {
    int i = blockIdx.x * blockDim.x + threadIdx.x;
    if (i < PP * NN) g_cnt[i] = 0;
    if (i < PP) g_w[i] = 0.f;
}

// ---------------- tf32 helpers ----------------
__device__ __forceinline__ uint32_t f2tf32(float x) {
    uint32_t r;
    asm("cvt.rna.tf32.f32 %0, %1;" : "=r"(r) : "f"(x));
    return r;
}
__device__ __forceinline__ void mma_tf32(float& c0, float& c1, float& c2, float& c3,
                                         uint32_t a0, uint32_t a1, uint32_t a2, uint32_t a3,
                                         uint32_t b0, uint32_t b1) {
    asm volatile("mma.sync.aligned.m16n8k8.row.col.f32.tf32.tf32.f32 "
                 "{%0,%1,%2,%3}, {%4,%5,%6,%7}, {%8,%9}, {%0,%1,%2,%3};"
                 : "+f"(c0), "+f"(c1), "+f"(c2), "+f"(c3)
                 : "r"(a0), "r"(a1), "r"(a2), "r"(a3), "r"(b0), "r"(b1));
}

// ---------------- K1: Wh = h @ W[p]  (tf32 hi/lo split) ----------------
__global__ __launch_bounds__(256) void k_gemm(const float* __restrict__ h,
                                              const float* __restrict__ W) {
    __shared__ uint32_t As_hi[64][17];
    __shared__ uint32_t As_lo[64][17];
    __shared__ uint32_t Bs_hi[16][132];
    __shared__ uint32_t Bs_lo[16][132];

    int p  = blockIdx.z;
    int m0 = blockIdx.x * 64;
    int n0 = blockIdx.y * 128;
    const float* B = W + (size_t)p * INF_ * HD_;
    int t    = threadIdx.x;
    int lane = t & 31;
    int w    = t >> 5;
    int warp_m = (w & 1) * 32;
    int warp_n = (w >> 1) * 32;
    int g   = lane >> 2;
    int tid = lane & 3;

    float acc[2][4][4];
    #pragma unroll
    for (int mt = 0; mt < 2; mt++)
        #pragma unroll
        for (int nt = 0; nt < 4; nt++)
            #pragma unroll
            for (int q = 0; q < 4; q++) acc[mt][nt][q] = 0.f;

    int a_row = t >> 2;
    int a_k4  = (t & 3) * 4;
    int gm_a  = m0 + a_row;
    const bool a_ok = gm_a < NN;

    for (int kk0 = 0; kk0 < INF_; kk0 += 16) {
        float4 va = a_ok ? *(const float4*)&h[(size_t)gm_a * INF_ + kk0 + a_k4]
                         : make_float4(0.f, 0.f, 0.f, 0.f);
        {
            float vv[4] = {va.x, va.y, va.z, va.w};
            #pragma unroll
            for (int j = 0; j < 4; j++) {
                uint32_t hb = f2tf32(vv[j]);
                As_hi[a_row][a_k4 + j] = hb;
                As_lo[a_row][a_k4 + j] = f2tf32(vv[j] - __uint_as_float(hb));
            }
        }
        #pragma unroll
        for (int i = 0; i < 2; i++) {
            int idx = t + i * 256;
            int bk  = idx >> 5;
            int bn4 = (idx & 31) * 4;
            float4 vb = *(const float4*)&B[(size_t)(kk0 + bk) * HD_ + n0 + bn4];
            float vv[4] = {vb.x, vb.y, vb.z, vb.w};
            #pragma unroll
            for (int j = 0; j < 4; j++) {
                uint32_t hb = f2tf32(vv[j]);
                Bs_hi[bk][bn4 + j] = hb;
                Bs_lo[bk][bn4 + j] = f2tf32(vv[j] - __uint_as_float(hb));
            }
        }
        __syncthreads();

        #pragma unroll
        for (int ks = 0; ks < 16; ks += 8) {
            uint32_t ah[2][4], alo[2][4];
            #pragma unroll
            for (int mt = 0; mt < 2; mt++) {
                int r0 = warp_m + mt * 16;
                ah[mt][0]  = As_hi[r0 + g    ][ks + tid];
                ah[mt][1]  = As_hi[r0 + g + 8][ks + tid];
                ah[mt][2]  = As_hi[r0 + g    ][ks + tid + 4];
                ah[mt][3]  = As_hi[r0 + g + 8][ks + tid + 4];
                alo[mt][0] = As_lo[r0 + g    ][ks + tid];
                alo[mt][1] = As_lo[r0 + g + 8][ks + tid];
                alo[mt][2] = As_lo[r0 + g    ][ks + tid + 4];
                alo[mt][3] = As_lo[r0 + g + 8][ks + tid + 4];
            }
            uint32_t bh[4][2], blo[4][2];
            #pragma unroll
            for (int nt = 0; nt < 4; nt++) {
                int c0 = warp_n + nt * 8 + g;
                bh[nt][0]  = Bs_hi[ks + tid    ][c0];
                bh[nt][1]  = Bs_hi[ks + tid + 4][c0];
                blo[nt][0] = Bs_lo[ks + tid    ][c0];
                blo[nt][1] = Bs_lo[ks + tid + 4][c0];
            }
            #pragma unroll
            for (int mt = 0; mt < 2; mt++)
                #pragma unroll
                for (int nt = 0; nt < 4; nt++) {
                    float* c = acc[mt][nt];
                    mma_tf32(c[0], c[1], c[2], c[3],
                             ah[mt][0], ah[mt][1], ah[mt][2], ah[mt][3],
                             bh[nt][0], bh[nt][1]);
                    mma_tf32(c[0], c[1], c[2], c[3],
                             ah[mt][0], ah[mt][1], ah[mt][2], ah[mt][3],
                             blo[nt][0], blo[nt][1]);
                    mma_tf32(c[0], c[1], c[2], c[3],
                             alo[mt][0], alo[mt][1], alo[mt][2], alo[mt][3],
                             bh[nt][0], bh[nt][1]);
                }
        }
        __syncthreads();
    }

    #pragma unroll
    for (int mt = 0; mt < 2; mt++) {
        int r0 = m0 + warp_m + mt * 16 + g;
        int r1 = r0 + 8;
        #pragma unroll
        for (int nt = 0; nt < 4; nt++) {
            int c = n0 + warp_n + nt * 8 + tid * 2;
            if (r0 < NN)
                *(float2*)&g_Wh[((size_t)p * NN + r0) * HD_ + c] =
                    make_float2(acc[mt][nt][0], acc[mt][nt][1]);
            if (r1 < NN)
                *(float2*)&g_Wh[((size_t)p * NN + r1) * HD_ + c] =
                    make_float2(acc[mt][nt][2], acc[mt][nt][3]);
        }
    }
}

// ---------------- K2: el/er = sum_d Wh * attn ----------------
__global__ void k_attn(const float* __restrict__ al, const float* __restrict__ ar) {
    int w    = (blockIdx.x * blockDim.x + threadIdx.x) >> 5;
    int lane = threadIdx.x & 31;
    int p = w / NN, n = w % NN;
    int head = lane >> 2;
    const float4* wh  = (const float4*)&g_Wh[((size_t)p * NN + n) * HD_ + lane * 16];
    const float4* a4l = (const float4*)&al[(p * HH + head) * DD + (lane & 3) * 16];
    const float4* a4r = (const float4*)&ar[(p * HH + head) * DD + (lane & 3) * 16];
    float sl = 0.f, sr = 0.f;
    #pragma unroll
    for (int q = 0; q < 4; q++) {
        float4 x = wh[q], l = a4l[q], r = a4r[q];
        sl += x.x * l.x + x.y * l.y + x.z * l.z + x.w * l.w;
        sr += x.x * r.x + x.y * r.y + x.z * r.z + x.w * r.w;
    }
    sl += __shfl_xor_sync(~0u, sl, 1); sl += __shfl_xor_sync(~0u, sl, 2);
    sr += __shfl_xor_sync(~0u, sr, 1); sr += __shfl_xor_sync(~0u, sr, 2);
    if ((lane & 3) == 0) {
        g_el[((size_t)p * NN + n) * HH + head] = sl;
        g_er[((size_t)p * NN + n) * HH + head] = sr;
    }
}

// ---------------- CSR build ----------------
__global__ void k_count(const int* __restrict__ edst) {
    int e = blockIdx.x * blockDim.x + threadIdx.x;
    int p = blockIdx.y;
    atomicAdd(&g_cnt[p * NN + edst[(size_t)p * EE + e]], 1);
}

// one block of 1024 threads per path; chunked scan (10 elems/thread)
__global__ __launch_bounds__(1024) void k_scan() {
    __shared__ int part[1024];
    int p = blockIdx.x;
    int t = threadIdx.x;
    const int CH = 10;
    int b = t * CH;
    int loc[CH];
    int sum = 0;
    #pragma unroll
    for (int i = 0; i < CH; i++) {
        int idx = b + i;
        int v = (idx < NN) ? g_cnt[p * NN + idx] : 0;
        loc[i] = sum;
        sum += v;
    }
    part[t] = sum;
    __syncthreads();
    // inclusive scan over part[1024]
    for (int ofs = 1; ofs < 1024; ofs <<= 1) {
        int val = (t >= ofs) ? part[t - ofs] : 0;
        __syncthreads();
        part[t] += val;
        __syncthreads();
    }
    int ex = part[t] - sum;   // exclusive base for this chunk
    #pragma unroll
    for (int i = 0; i < CH; i++) {
        int idx = b + i;
        if (idx < NN) {
            int o = ex + loc[i];
            g_off[p * NN + idx] = o;
            g_pos[p * NN + idx] = o;
        }
    }
}

__global__ void k_scatter(const int* __restrict__ edst) {
    int e = blockIdx.x * blockDim.x + threadIdx.x;
    int p = blockIdx.y;
    int d = edst[(size_t)p * EE + e];
    int pos = atomicAdd(&g_pos[p * NN + d], 1);
    g_eid[(size_t)p * EE + pos] = e;
}

// ---------------- K3: edge pass A: ex = exp(leakyrelu(el[src]+er[dst])) ----------------
__global__ void k_edgeA(const int* __restrict__ esrc, const int* __restrict__ edst) {
    int e = blockIdx.x * blockDim.x + threadIdx.x;
    int p = blockIdx.y;
    int s = esrc[(size_t)p * EE + e];
    int d = edst[(size_t)p * EE + e];
    const float4* el4 = (const float4*)&g_el[((size_t)p * NN + s) * HH];
    const float4* er4 = (const float4*)&g_er[((size_t)p * NN + d) * HH];
    float4*       ex4 = (float4*)&g_ex[((size_t)p * EE + e) * HH];
    #pragma unroll
    for (int q = 0; q < 2; q++) {
        float4 l = el4[q], r = er4[q];
        float v[4] = {l.x + r.x, l.y + r.y, l.z + r.z, l.w + r.w};
        float x[4];
        #pragma unroll
        for (int j = 0; j < 4; j++) {
            float vv = v[j] > 0.f ? v[j] : NEG_SLOPE * v[j];
            x[j] = expf(vv);              // shift-free softmax (safe range)
        }
        ex4[q] = make_float4(x[0], x[1], x[2], x[3]);
    }
}

// ---------------- K4: gather: z[d] = elu( (sum ex*Wh[src]) / (sum ex) + b ) ----------
// one warp per (p, d). grid: (N/8, P), block 256
__global__ __launch_bounds__(256) void k_gather(const int* __restrict__ esrc,
                                                const float* __restrict__ gb) {
    int lane = threadIdx.x & 31;
    int d = blockIdx.x * 8 + (threadIdx.x >> 5);
    int p = blockIdx.y;
    int head = lane >> 2;

    int start = g_off[p * NN + d];
    int deg   = g_cnt[p * NN + d];
    const int* eid = &g_eid[(size_t)p * EE + start];
    const int* es  = &esrc[(size_t)p * EE];

    float acc[16];
    #pragma unroll
    for (int q = 0; q < 16; q++) acc[q] = 0.f;
    float ssum = 0.f;

    int e_cur = (deg > 0) ? eid[0] : 0;
    int s_cur = (deg > 0) ? es[e_cur] : 0;
    for (int j = 0; j < deg; j++) {
        int e_nxt = (j + 1 < deg) ? eid[j + 1] : 0;
        int s_nxt = (j + 1 < deg) ? es[e_nxt] : 0;
        float xv = g_ex[((size_t)p * EE + e_cur) * HH + head];
        ssum += xv;
        const float4* src4 = (const float4*)&g_Wh[((size_t)p * NN + s_cur) * HD_ + lane * 16];
        #pragma unroll
        for (int q = 0; q < 4; q++) {
            float4 v = src4[q];
            acc[4 * q + 0] += xv * v.x;
            acc[4 * q + 1] += xv * v.y;
            acc[4 * q + 2] += xv * v.z;
            acc[4 * q + 3] += xv * v.w;
        }
        e_cur = e_nxt; s_cur = s_nxt;
    }

    float inv = (ssum > 0.f) ? 1.f / ssum : 0.f;
    float* dst = &g_z[((size_t)p * NN + d) * HD_ + lane * 16];
    const float* bp = &gb[p * HD_ + lane * 16];
    #pragma unroll
    for (int q = 0; q < 4; q++) {
        float4 b4 = *(const float4*)&bp[q * 4];
        float o[4];
        o[0] = acc[4 * q + 0] * inv + b4.x;
        o[1] = acc[4 * q + 1] * inv + b4.y;
        o[2] = acc[4 * q + 2] * inv + b4.z;
        o[3] = acc[4 * q + 3] * inv + b4.w;
        #pragma unroll
        for (int j = 0; j < 4; j++) o[j] = o[j] > 0.f ? o[j] : expm1f(o[j]);
        *(float4*)&dst[q * 4] = make_float4(o[0], o[1], o[2], o[3]);
    }
}

// ---------------- K5: semantic partial: w[p] += tanh(z@W1+b1)@W2 ----------------
__global__ void k_post(const float* __restrict__ W1, const float* __restrict__ b1,
                       const float* __restrict__ W2) {
    __shared__ float zs[8 * HD_];
    __shared__ float w1s[64 * 64];
    __shared__ float red[256];
    int p  = blockIdx.y;
    int n0 = blockIdx.x * 8;
    int t  = threadIdx.x;
    for (int i = t; i < 8 * HD_; i += 256) {
        int node = i >> 9, c = i & 511;
        zs[i] = g_z[((size_t)p * NN + n0 + node) * HD_ + c];
    }
    __syncthreads();
    int j = t & 63, grp = t >> 6;
    float acc0 = 0.f, acc1 = 0.f;
    for (int kc = 0; kc < 8; kc++) {
        for (int i = t; i < 64 * 64; i += 256)
            w1s[i] = W1[(size_t)(kc * 64 + (i >> 6)) * 64 + (i & 63)];
        __syncthreads();
        #pragma unroll
        for (int k = 0; k < 64; k++) {
            float w1 = w1s[k * 64 + j];
            int zb = kc * 64 + k;
            acc0 += zs[(grp * 2 + 0) * HD_ + zb] * w1;
            acc1 += zs[(grp * 2 + 1) * HD_ + zb] * w1;
        }
        __syncthreads();
    }
    float b = b1[j], w2 = W2[j];
    float contrib = tanhf(acc0 + b) * w2 + tanhf(acc1 + b) * w2;
    red[t] = contrib;
    __syncthreads();
    for (int ofs = 128; ofs > 0; ofs >>= 1) {
        if (t < ofs) red[t] += red[t + ofs];
        __syncthreads();
    }
    if (t == 0) atomicAdd(&g_w[p], red[0]);
}

// ---------------- K6: beta = softmax(w / N) ----------------
__global__ void k_beta() {
    if (threadIdx.x == 0) {
        float w[PP], m = -1e30f;
        #pragma unroll
        for (int p = 0; p < PP; p++) { w[p] = g_w[p] / (float)NN; m = fmaxf(m, w[p]); }
        float s = 0.f;
        #pragma unroll
        for (int p = 0; p < PP; p++) { w[p] = expf(w[p] - m); s += w[p]; }
        #pragma unroll
        for (int p = 0; p < PP; p++) g_beta[p] = w[p] / s;
    }
}

// ---------------- K7: out = sum_p beta[p] * z[p] ----------------
__global__ void k_comb(float* __restrict__ out) {
    int i = blockIdx.x * blockDim.x + threadIdx.x;
    const float4* z = (const float4*)g_z;
    const size_t stride = (size_t)NN * HD_ / 4;
    float b0 = g_beta[0], b1 = g_beta[1], b2 = g_beta[2], b3 = g_beta[3];
    float4 a = z[i];
    float4 b = z[i + stride];
    float4 c = z[i + 2 * stride];
    float4 d = z[i + 3 * stride];
    float4 o;
    o.x = b0 * a.x + b1 * b.x + b2 * c.x + b3 * d.x;
    o.y = b0 * a.y + b1 * b.y + b2 * c.y + b3 * d.y;
    o.z = b0 * a.z + b1 * b.z + b2 * c.z + b3 * d.z;
    o.w = b0 * a.w + b1 * b.w + b2 * c.w + b3 * d.w;
    ((float4*)out)[i] = o;
}

// ---------------- launcher ----------------
extern "C" void kernel_launch(void* const* d_in, const int* in_sizes, int n_in,
                              void* d_out, int out_size) {
    const float* h     = (const float*)d_in[0];
    const int*   esrc  = (const int*)  d_in[1];
    const int*   edst  = (const int*)  d_in[2];
    const float* gat_W = (const float*)d_in[3];
    const float* al    = (const float*)d_in[4];
    const float* ar    = (const float*)d_in[5];
    const float* gat_b = (const float*)d_in[6];
    const float* sW1   = (const float*)d_in[7];
    const float* sb1   = (const float*)d_in[8];
    const float* sW2   = (const float*)d_in[9];
    float* out = (float*)d_out;

    k_zero<<<(PP * NN + 255) / 256, 256>>>();

    dim3 ge(EE / 256, PP);
    k_count<<<ge, 256>>>(edst);
    k_scan<<<PP, 1024>>>();
    k_scatter<<<ge, 256>>>(edst);

    dim3 gg((NN + 63) / 64, HD_ / 128, PP);
    k_gemm<<<gg, 256>>>(h, gat_W);

    k_attn<<<(PP * NN) / 8, 256>>>(al, ar);

    k_edgeA<<<ge, 256>>>(esrc, edst);

    dim3 gga((NN + 7) / 8, PP);
    k_gather<<<gga, 256>>>(esrc, gat_b);

    dim3 gp(NN / 8, PP);
    k_post<<<gp, 256>>>(sW1, sb1, sW2);

    k_beta<<<1, 32>>>();

    k_comb<<<(NN * HD_ / 4) / 256, 256>>>(out);
}

// round 5
// speedup vs baseline: 1.8994x; 1.2835x over previous
#include <cuda_runtime.h>
#include <cuda_bf16.h>
#include <cstdint>

#define NN   10000
#define NPAD 10048          // 157*64
#define PP   4
#define EE   160000
#define INF_ 256
#define HH   8
#define DD   64
#define HD_  512
#define NEG_SLOPE 0.2f

// ---------------- device scratch ----------------
__device__ float g_Wh[(size_t)PP * NN * HD_];
__device__ float g_z [(size_t)PP * NN * HD_];
__device__ float g_el[(size_t)PP * NN * HH];
__device__ float g_er[(size_t)PP * NN * HH];
__device__ float g_exp[(size_t)PP * EE * HH];     // exp(leakyrelu), CSR-permuted order
__device__ int   g_cnt[PP * NN];
__device__ int   g_off[PP * NN];
__device__ int   g_pos[PP * NN];
__device__ int   g_sperm[(size_t)PP * EE];        // src node per CSR slot
__device__ int   g_dperm[(size_t)PP * EE];        // dst node per CSR slot
__device__ __nv_bfloat16 g_h_hi[(size_t)NPAD * INF_];   // pad rows stay zero-init
__device__ __nv_bfloat16 g_h_lo[(size_t)NPAD * INF_];
__device__ __nv_bfloat16 g_W_hi[(size_t)PP * HD_ * INF_];  // transposed [p][n][k]
__device__ __nv_bfloat16 g_W_lo[(size_t)PP * HD_ * INF_];
__device__ float g_w [PP];
__device__ float g_beta[PP];

// ---------------- K0: zero counters ----------------
__global__ void k_zero() {
    int i = blockIdx.x * blockDim.x + threadIdx.x;
    if (i < PP * NN) g_cnt[i] = 0;
    if (i < PP) g_w[i] = 0.f;
}

// ---------------- convert h to bf16 hi/lo ----------------
__global__ void k_cvt_h(const float* __restrict__ h) {
    int i = blockIdx.x * blockDim.x + threadIdx.x;
    if (i < NN * INF_) {
        float v = h[i];
        __nv_bfloat16 hi = __float2bfloat16(v);
        g_h_hi[i] = hi;
        g_h_lo[i] = __float2bfloat16(v - __bfloat162float(hi));
    }
}

// ---------------- convert + transpose W: [p][k][n] -> [p][n][k] hi/lo ----------------
__global__ void k_cvt_W(const float* __restrict__ W) {
    __shared__ float tile[32][33];
    int p  = blockIdx.z;
    int k0 = blockIdx.x * 32;
    int n0 = blockIdx.y * 32;
    int tx = threadIdx.x, ty0 = threadIdx.y;
    for (int ty = ty0; ty < 32; ty += 8)
        tile[ty][tx] = W[(size_t)p * INF_ * HD_ + (size_t)(k0 + ty) * HD_ + n0 + tx];
    __syncthreads();
    for (int ty = ty0; ty < 32; ty += 8) {
        float v = tile[tx][ty];   // = W[p][k0+tx][n0+ty]
        __nv_bfloat16 hi = __float2bfloat16(v);
        size_t oi = (size_t)p * HD_ * INF_ + (size_t)(n0 + ty) * INF_ + k0 + tx;
        g_W_hi[oi] = hi;
        g_W_lo[oi] = __float2bfloat16(v - __bfloat162float(hi));
    }
}

// ---------------- bf16 mma helper ----------------
__device__ __forceinline__ void mma_bf16(float& c0, float& c1, float& c2, float& c3,
                                         uint32_t a0, uint32_t a1, uint32_t a2, uint32_t a3,
                                         uint32_t b0, uint32_t b1) {
    asm volatile("mma.sync.aligned.m16n8k16.row.col.f32.bf16.bf16.f32 "
                 "{%0,%1,%2,%3}, {%4,%5,%6,%7}, {%8,%9}, {%0,%1,%2,%3};"
                 : "+f"(c0), "+f"(c1), "+f"(c2), "+f"(c3)
                 : "r"(a0), "r"(a1), "r"(a2), "r"(a3), "r"(b0), "r"(b1));
}

// ---------------- K1: Wh = h @ W[p] (bf16 hi/lo, 3-term) + fused el/er epilogue ----
// BM=64, BN=128, BK=32. 256 threads = 8 warps (warp tile 32x32).
// grid: (157, 4, P)
__global__ __launch_bounds__(256) void k_gemm(const float* __restrict__ al,
                                              const float* __restrict__ ar) {
    __shared__ __nv_bfloat16 As_hi[64][40];
    __shared__ __nv_bfloat16 As_lo[64][40];
    __shared__ __nv_bfloat16 Bs_hi[128][40];
    __shared__ __nv_bfloat16 Bs_lo[128][40];
    __shared__ float s_att[64][2][2];   // [row][head-within-block][el/er]

    int p  = blockIdx.z;
    int m0 = blockIdx.x * 64;
    int n0 = blockIdx.y * 128;
    int t    = threadIdx.x;
    int lane = t & 31;
    int w    = t >> 5;
    int warp_m = (w & 1) * 32;
    int warp_n = (w >> 1) * 32;
    int g   = lane >> 2;
    int tid = lane & 3;

    float acc[2][4][4];
    #pragma unroll
    for (int mt = 0; mt < 2; mt++)
        #pragma unroll
        for (int nt = 0; nt < 4; nt++)
            #pragma unroll
            for (int q = 0; q < 4; q++) acc[mt][nt][q] = 0.f;

    // A tile load mapping: thread -> (row, koff)
    int a_row  = t >> 2;
    int a_koff = (t & 3) * 8;
    const __nv_bfloat16* ah_base = &g_h_hi[(size_t)(m0 + a_row) * INF_ + a_koff];
    const __nv_bfloat16* alo_base = &g_h_lo[(size_t)(m0 + a_row) * INF_ + a_koff];
    // B tile: 2 chunks per thread
    int b_n0   = t >> 2;            // chunk0 row
    int b_k0   = (t & 3) * 8;
    int b_n1   = (t + 256) >> 2;    // chunk1 row
    int b_k1   = ((t + 256) & 3) * 8;
    const __nv_bfloat16* bW = &g_W_hi[(size_t)p * HD_ * INF_ + (size_t)n0 * INF_];
    const __nv_bfloat16* bWl = &g_W_lo[(size_t)p * HD_ * INF_ + (size_t)n0 * INF_];

    uint4 pa_hi, pa_lo, pb_hi0, pb_hi1, pb_lo0, pb_lo1;
    // prefetch kb=0
    pa_hi  = *(const uint4*)&ah_base[0];
    pa_lo  = *(const uint4*)&alo_base[0];
    pb_hi0 = *(const uint4*)&bW [(size_t)b_n0 * INF_ + b_k0];
    pb_hi1 = *(const uint4*)&bW [(size_t)b_n1 * INF_ + b_k1];
    pb_lo0 = *(const uint4*)&bWl[(size_t)b_n0 * INF_ + b_k0];
    pb_lo1 = *(const uint4*)&bWl[(size_t)b_n1 * INF_ + b_k1];

    for (int kb = 0; kb < 8; kb++) {
        __syncthreads();
        *(uint4*)&As_hi[a_row][a_koff] = pa_hi;
        *(uint4*)&As_lo[a_row][a_koff] = pa_lo;
        *(uint4*)&Bs_hi[b_n0][b_k0]    = pb_hi0;
        *(uint4*)&Bs_hi[b_n1][b_k1]    = pb_hi1;
        *(uint4*)&Bs_lo[b_n0][b_k0]    = pb_lo0;
        *(uint4*)&Bs_lo[b_n1][b_k1]    = pb_lo1;
        __syncthreads();
        if (kb < 7) {
            int kk = (kb + 1) * 32;
            pa_hi  = *(const uint4*)&ah_base[kk];
            pa_lo  = *(const uint4*)&alo_base[kk];
            pb_hi0 = *(const uint4*)&bW [(size_t)b_n0 * INF_ + kk + b_k0];
            pb_hi1 = *(const uint4*)&bW [(size_t)b_n1 * INF_ + kk + b_k1];
            pb_lo0 = *(const uint4*)&bWl[(size_t)b_n0 * INF_ + kk + b_k0];
            pb_lo1 = *(const uint4*)&bWl[(size_t)b_n1 * INF_ + kk + b_k1];
        }
        #pragma unroll
        for (int ks = 0; ks < 32; ks += 16) {
            uint32_t ahf[2][4], alf[2][4];
            #pragma unroll
            for (int mt = 0; mt < 2; mt++) {
                int r0 = warp_m + mt * 16 + g;
                ahf[mt][0] = *(const uint32_t*)&As_hi[r0    ][ks + tid * 2];
                ahf[mt][1] = *(const uint32_t*)&As_hi[r0 + 8][ks + tid * 2];
                ahf[mt][2] = *(const uint32_t*)&As_hi[r0    ][ks + tid * 2 + 8];
                ahf[mt][3] = *(const uint32_t*)&As_hi[r0 + 8][ks + tid * 2 + 8];
                alf[mt][0] = *(const uint32_t*)&As_lo[r0    ][ks + tid * 2];
                alf[mt][1] = *(const uint32_t*)&As_lo[r0 + 8][ks + tid * 2];
                alf[mt][2] = *(const uint32_t*)&As_lo[r0    ][ks + tid * 2 + 8];
                alf[mt][3] = *(const uint32_t*)&As_lo[r0 + 8][ks + tid * 2 + 8];
            }
            uint32_t bhf[4][2], blf[4][2];
            #pragma unroll
            for (int nt = 0; nt < 4; nt++) {
                int c0 = warp_n + nt * 8 + g;
                bhf[nt][0] = *(const uint32_t*)&Bs_hi[c0][ks + tid * 2];
                bhf[nt][1] = *(const uint32_t*)&Bs_hi[c0][ks + tid * 2 + 8];
                blf[nt][0] = *(const uint32_t*)&Bs_lo[c0][ks + tid * 2];
                blf[nt][1] = *(const uint32_t*)&Bs_lo[c0][ks + tid * 2 + 8];
            }
            #pragma unroll
            for (int mt = 0; mt < 2; mt++)
                #pragma unroll
                for (int nt = 0; nt < 4; nt++) {
                    float* c = acc[mt][nt];
                    mma_bf16(c[0], c[1], c[2], c[3],
                             ahf[mt][0], ahf[mt][1], ahf[mt][2], ahf[mt][3],
                             bhf[nt][0], bhf[nt][1]);
                    mma_bf16(c[0], c[1], c[2], c[3],
                             ahf[mt][0], ahf[mt][1], ahf[mt][2], ahf[mt][3],
                             blf[nt][0], blf[nt][1]);
                    mma_bf16(c[0], c[1], c[2], c[3],
                             alf[mt][0], alf[mt][1], alf[mt][2], alf[mt][3],
                             bhf[nt][0], bhf[nt][1]);
                }
        }
    }

    // ---- store Wh ----
    #pragma unroll
    for (int mt = 0; mt < 2; mt++) {
        int r0 = m0 + warp_m + mt * 16 + g;
        int r1 = r0 + 8;
        #pragma unroll
        for (int nt = 0; nt < 4; nt++) {
            int c = n0 + warp_n + nt * 8 + tid * 2;
            if (r0 < NN)
                *(float2*)&g_Wh[((size_t)p * NN + r0) * HD_ + c] =
                    make_float2(acc[mt][nt][0], acc[mt][nt][1]);
            if (r1 < NN)
                *(float2*)&g_Wh[((size_t)p * NN + r1) * HD_ + c] =
                    make_float2(acc[mt][nt][2], acc[mt][nt][3]);
        }
    }

    // ---- fused attention dot-products (el/er for the 2 heads this block owns) ----
    int head0 = n0 >> 6;             // global head of cols n0..n0+63
    int hw = warp_n >= 64;           // which of the 2 block heads this warp contributes to
    int dbase = (warp_n & 32);
    const float* alp = &al[((size_t)p * HH + head0 + hw) * DD];
    const float* arp = &ar[((size_t)p * HH + head0 + hw) * DD];

    s_att[t >> 2][(t >> 1) & 1][t & 1] = 0.f;
    __syncthreads();

    #pragma unroll
    for (int mt = 0; mt < 2; mt++) {
        #pragma unroll
        for (int rr = 0; rr < 2; rr++) {
            float pel = 0.f, per_ = 0.f;
            #pragma unroll
            for (int nt = 0; nt < 4; nt++) {
                #pragma unroll
                for (int j = 0; j < 2; j++) {
                    float c = acc[mt][nt][rr * 2 + j];
                    int dd = dbase + nt * 8 + tid * 2 + j;
                    pel  += c * alp[dd];
                    per_ += c * arp[dd];
                }
            }
            pel  += __shfl_xor_sync(~0u, pel, 1);  pel  += __shfl_xor_sync(~0u, pel, 2);
            per_ += __shfl_xor_sync(~0u, per_, 1); per_ += __shfl_xor_sync(~0u, per_, 2);
            if (tid == 0) {
                int row = warp_m + mt * 16 + g + rr * 8;
                atomicAdd(&s_att[row][hw][0], pel);
                atomicAdd(&s_att[row][hw][1], per_);
            }
        }
    }
    __syncthreads();
    {
        int row = t >> 2, h2 = (t >> 1) & 1, lr = t & 1;
        int gr = m0 + row;
        if (gr < NN) {
            float v = s_att[row][h2][lr];
            size_t idx = ((size_t)p * NN + gr) * HH + head0 + h2;
            if (lr == 0) g_el[idx] = v; else g_er[idx] = v;
        }
    }
}

// ---------------- CSR build ----------------
__global__ void k_count(const int* __restrict__ edst) {
    int e = blockIdx.x * blockDim.x + threadIdx.x;
    int p = blockIdx.y;
    atomicAdd(&g_cnt[p * NN + edst[(size_t)p * EE + e]], 1);
}

__global__ __launch_bounds__(1024) void k_scan() {
    __shared__ int part[1024];
    int p = blockIdx.x;
    int t = threadIdx.x;
    const int CH = 10;
    int b = t * CH;
    int loc[CH];
    int sum = 0;
    #pragma unroll
    for (int i = 0; i < CH; i++) {
        int idx = b + i;
        int v = (idx < NN) ? g_cnt[p * NN + idx] : 0;
        loc[i] = sum;
        sum += v;
    }
    part[t] = sum;
    __syncthreads();
    for (int ofs = 1; ofs < 1024; ofs <<= 1) {
        int val = (t >= ofs) ? part[t - ofs] : 0;
        __syncthreads();
        part[t] += val;
        __syncthreads();
    }
    int ex = part[t] - sum;
    #pragma unroll
    for (int i = 0; i < CH; i++) {
        int idx = b + i;
        if (idx < NN) {
            int o = ex + loc[i];
            g_off[p * NN + idx] = o;
            g_pos[p * NN + idx] = o;
        }
    }
}

__global__ void k_scatter(const int* __restrict__ esrc, const int* __restrict__ edst) {
    int e = blockIdx.x * blockDim.x + threadIdx.x;
    int p = blockIdx.y;
    int d = edst[(size_t)p * EE + e];
    int s = esrc[(size_t)p * EE + e];
    int pos = atomicAdd(&g_pos[p * NN + d], 1);
    g_sperm[(size_t)p * EE + pos] = s;
    g_dperm[(size_t)p * EE + pos] = d;
}

// ---------------- K3: exp(leakyrelu(el[s]+er[d])) in CSR order ----------------
__global__ void k_edgeA() {
    int i = blockIdx.x * blockDim.x + threadIdx.x;
    int p = blockIdx.y;
    int s = g_sperm[(size_t)p * EE + i];
    int d = g_dperm[(size_t)p * EE + i];
    const float4* el4 = (const float4*)&g_el[((size_t)p * NN + s) * HH];
    const float4* er4 = (const float4*)&g_er[((size_t)p * NN + d) * HH];
    float4*       ex4 = (float4*)&g_exp[((size_t)p * EE + i) * HH];
    #pragma unroll
    for (int q = 0; q < 2; q++) {
        float4 l = el4[q], r = er4[q];
        float v[4] = {l.x + r.x, l.y + r.y, l.z + r.z, l.w + r.w};
        float x[4];
        #pragma unroll
        for (int j = 0; j < 4; j++) {
            float vv = v[j] > 0.f ? v[j] : NEG_SLOPE * v[j];
            x[j] = expf(vv);            // shift-free softmax (safe range)
        }
        ex4[q] = make_float4(x[0], x[1], x[2], x[3]);
    }
}

// ---------------- K4: gather: z[d] = elu((sum ex*Wh[src])/(sum ex) + b) ----------
// one warp per (p, d); sequential sperm/exp reads, 2-way unrolled Wh gather.
__global__ __launch_bounds__(256) void k_gather(const float* __restrict__ gb) {
    int lane = threadIdx.x & 31;
    int d = blockIdx.x * 8 + (threadIdx.x >> 5);
    int p = blockIdx.y;
    int head = lane >> 2;

    int start = g_off[p * NN + d];
    int deg   = g_cnt[p * NN + d];
    const int*   sp = &g_sperm[(size_t)p * EE + start];
    const float* xp = &g_exp[((size_t)p * EE + start) * HH + head];
    const float* whb = &g_Wh[(size_t)p * NN * HD_ + lane * 16];

    float acc[16];
    #pragma unroll
    for (int q = 0; q < 16; q++) acc[q] = 0.f;
    float ssum = 0.f;

    int j = 0;
    for (; j + 1 < deg; j += 2) {
        int s0 = sp[j], s1 = sp[j + 1];
        float xv0 = xp[(size_t)j * HH];
        float xv1 = xp[(size_t)(j + 1) * HH];
        const float4* a4 = (const float4*)&whb[(size_t)s0 * HD_];
        const float4* b4 = (const float4*)&whb[(size_t)s1 * HD_];
        float4 va0 = a4[0], va1 = a4[1], va2 = a4[2], va3 = a4[3];
        float4 vb0 = b4[0], vb1 = b4[1], vb2 = b4[2], vb3 = b4[3];
        ssum += xv0 + xv1;
        acc[0]  += xv0 * va0.x + xv1 * vb0.x;  acc[1]  += xv0 * va0.y + xv1 * vb0.y;
        acc[2]  += xv0 * va0.z + xv1 * vb0.z;  acc[3]  += xv0 * va0.w + xv1 * vb0.w;
        acc[4]  += xv0 * va1.x + xv1 * vb1.x;  acc[5]  += xv0 * va1.y + xv1 * vb1.y;
        acc[6]  += xv0 * va1.z + xv1 * vb1.z;  acc[7]  += xv0 * va1.w + xv1 * vb1.w;
        acc[8]  += xv0 * va2.x + xv1 * vb2.x;  acc[9]  += xv0 * va2.y + xv1 * vb2.y;
        acc[10] += xv0 * va2.z + xv1 * vb2.z;  acc[11] += xv0 * va2.w + xv1 * vb2.w;
        acc[12] += xv0 * va3.x + xv1 * vb3.x;  acc[13] += xv0 * va3.y + xv1 * vb3.y;
        acc[14] += xv0 * va3.z + xv1 * vb3.z;  acc[15] += xv0 * va3.w + xv1 * vb3.w;
    }
    if (j < deg) {
        int s0 = sp[j];
        float xv0 = xp[(size_t)j * HH];
        const float4* a4 = (const float4*)&whb[(size_t)s0 * HD_];
        ssum += xv0;
        #pragma unroll
        for (int q = 0; q < 4; q++) {
            float4 v = a4[q];
            acc[4 * q + 0] += xv0 * v.x;  acc[4 * q + 1] += xv0 * v.y;
            acc[4 * q + 2] += xv0 * v.z;  acc[4 * q + 3] += xv0 * v.w;
        }
    }

    float inv = (ssum > 0.f) ? 1.f / ssum : 0.f;
    float* dst = &g_z[((size_t)p * NN + d) * HD_ + lane * 16];
    const float* bp = &gb[p * HD_ + lane * 16];
    #pragma unroll
    for (int q = 0; q < 4; q++) {
        float4 b4 = *(const float4*)&bp[q * 4];
        float o[4];
        o[0] = acc[4 * q + 0] * inv + b4.x;
        o[1] = acc[4 * q + 1] * inv + b4.y;
        o[2] = acc[4 * q + 2] * inv + b4.z;
        o[3] = acc[4 * q + 3] * inv + b4.w;
        #pragma unroll
        for (int jj = 0; jj < 4; jj++) o[jj] = o[jj] > 0.f ? o[jj] : expm1f(o[jj]);
        *(float4*)&dst[q * 4] = make_float4(o[0], o[1], o[2], o[3]);
    }
}

// ---------------- K5: semantic partial: w[p] += tanh(z@W1+b1)@W2 ----------------
__global__ void k_post(const float* __restrict__ W1, const float* __restrict__ b1,
                       const float* __restrict__ W2) {
    __shared__ float zs[8 * HD_];
    __shared__ float w1s[64 * 64];
    __shared__ float red[256];
    int p  = blockIdx.y;
    int n0 = blockIdx.x * 8;
    int t  = threadIdx.x;
    for (int i = t; i < 8 * HD_; i += 256) {
        int node = i >> 9, c = i & 511;
        zs[i] = g_z[((size_t)p * NN + n0 + node) * HD_ + c];
    }
    __syncthreads();
    int j = t & 63, grp = t >> 6;
    float acc0 = 0.f, acc1 = 0.f;
    for (int kc = 0; kc < 8; kc++) {
        for (int i = t; i < 64 * 64; i += 256)
            w1s[i] = W1[(size_t)(kc * 64 + (i >> 6)) * 64 + (i & 63)];
        __syncthreads();
        #pragma unroll
        for (int k = 0; k < 64; k++) {
            float w1 = w1s[k * 64 + j];
            int zb = kc * 64 + k;
            acc0 += zs[(grp * 2 + 0) * HD_ + zb] * w1;
            acc1 += zs[(grp * 2 + 1) * HD_ + zb] * w1;
        }
        __syncthreads();
    }
    float b = b1[j], w2 = W2[j];
    float contrib = tanhf(acc0 + b) * w2 + tanhf(acc1 + b) * w2;
    red[t] = contrib;
    __syncthreads();
    for (int ofs = 128; ofs > 0; ofs >>= 1) {
        if (t < ofs) red[t] += red[t + ofs];
        __syncthreads();
    }
    if (t == 0) atomicAdd(&g_w[p], red[0]);
}

// ---------------- K6: beta = softmax(w / N) ----------------
__global__ void k_beta() {
    if (threadIdx.x == 0) {
        float w[PP], m = -1e30f;
        #pragma unroll
        for (int p = 0; p < PP; p++) { w[p] = g_w[p] / (float)NN; m = fmaxf(m, w[p]); }
        float s = 0.f;
        #pragma unroll
        for (int p = 0; p < PP; p++) { w[p] = expf(w[p] - m); s += w[p]; }
        #pragma unroll
        for (int p = 0; p < PP; p++) g_beta[p] = w[p] / s;
    }
}

// ---------------- K7: out = sum_p beta[p] * z[p] ----------------
__global__ void k_comb(float* __restrict__ out) {
    int i = blockIdx.x * blockDim.x + threadIdx.x;
    const float4* z = (const float4*)g_z;
    const size_t stride = (size_t)NN * HD_ / 4;
    float b0 = g_beta[0], b1 = g_beta[1], b2 = g_beta[2], b3 = g_beta[3];
    float4 a = z[i];
    float4 b = z[i + stride];
    float4 c = z[i + 2 * stride];
    float4 d = z[i + 3 * stride];
    float4 o;
    o.x = b0 * a.x + b1 * b.x + b2 * c.x + b3 * d.x;
    o.y = b0 * a.y + b1 * b.y + b2 * c.y + b3 * d.y;
    o.z = b0 * a.z + b1 * b.z + b2 * c.z + b3 * d.z;
    o.w = b0 * a.w + b1 * b.w + b2 * c.w + b3 * d.w;
    ((float4*)out)[i] = o;
}

// ---------------- launcher ----------------
extern "C" void kernel_launch(void* const* d_in, const int* in_sizes, int n_in,
                              void* d_out, int out_size) {
    const float* h     = (const float*)d_in[0];
    const int*   esrc  = (const int*)  d_in[1];
    const int*   edst  = (const int*)  d_in[2];
    const float* gat_W = (const float*)d_in[3];
    const float* al    = (const float*)d_in[4];
    const float* ar    = (const float*)d_in[5];
    const float* gat_b = (const float*)d_in[6];
    const float* sW1   = (const float*)d_in[7];
    const float* sb1   = (const float*)d_in[8];
    const float* sW2   = (const float*)d_in[9];
    float* out = (float*)d_out;

    k_zero<<<(PP * NN + 255) / 256, 256>>>();

    k_cvt_h<<<(NN * INF_ + 255) / 256, 256>>>(h);
    dim3 gw(INF_ / 32, HD_ / 32, PP);
    k_cvt_W<<<gw, dim3(32, 8)>>>(gat_W);

    dim3 ge(EE / 256, PP);
    k_count<<<ge, 256>>>(edst);
    k_scan<<<PP, 1024>>>();
    k_scatter<<<ge, 256>>>(esrc, edst);

    dim3 gg((NN + 63) / 64, HD_ / 128, PP);
    k_gemm<<<gg, 256>>>(al, ar);

    k_edgeA<<<ge, 256>>>();

    dim3 gga((NN + 7) / 8, PP);
    k_gather<<<gga, 256>>>(gat_b);

    dim3 gp(NN / 8, PP);
    k_post<<<gp, 256>>>(sW1, sb1, sW2);

    k_beta<<<1, 32>>>();

    k_comb<<<(NN * HD_ / 4) / 256, 256>>>(out);
}

// round 6
// speedup vs baseline: 1.9182x; 1.0099x over previous
#include <cuda_runtime.h>
#include <cuda_bf16.h>
#include <cstdint>

#define NN   10000
#define NPAD 10048          // 157*64
#define PP   4
#define EE   160000
#define INF_ 256
#define HH   8
#define DD   64
#define HD_  512
#define NEG_SLOPE 0.2f

// ---------------- device scratch ----------------
__device__ float g_Wh[(size_t)PP * NN * HD_];
__device__ float g_z [(size_t)PP * NN * HD_];
__device__ float g_el[(size_t)PP * NN * HH];
__device__ float g_er[(size_t)PP * NN * HH];
__device__ float g_exp[(size_t)PP * EE * HH];     // exp(leakyrelu), CSR order
__device__ int   g_cnt[PP * NN];
__device__ int   g_off[PP * NN];
__device__ int   g_pos[PP * NN];
__device__ int   g_sperm[(size_t)PP * EE];
__device__ int   g_dperm[(size_t)PP * EE];
__device__ __nv_bfloat16 g_h_hi[(size_t)NPAD * INF_];   // pad rows stay zero
__device__ __nv_bfloat16 g_h_lo[(size_t)NPAD * INF_];
__device__ __nv_bfloat16 g_W_hi[(size_t)PP * HD_ * INF_];  // [p][n][k]
__device__ __nv_bfloat16 g_W_lo[(size_t)PP * HD_ * INF_];
__device__ float g_w [PP];
__device__ float g_beta[PP];

// ---------------- K0 ----------------
__global__ void k_zero() {
    int i = blockIdx.x * blockDim.x + threadIdx.x;
    if (i < PP * NN) g_cnt[i] = 0;
    if (i < PP) g_w[i] = 0.f;
}

// ---------------- convert h to bf16 hi/lo ----------------
__global__ void k_cvt_h(const float* __restrict__ h) {
    int i = blockIdx.x * blockDim.x + threadIdx.x;
    if (i < NN * INF_) {
        float v = h[i];
        __nv_bfloat16 hi = __float2bfloat16(v);
        g_h_hi[i] = hi;
        g_h_lo[i] = __float2bfloat16(v - __bfloat162float(hi));
    }
}

// ---------------- convert + transpose W ----------------
__global__ void k_cvt_W(const float* __restrict__ W) {
    __shared__ float tile[32][33];
    int p  = blockIdx.z;
    int k0 = blockIdx.x * 32;
    int n0 = blockIdx.y * 32;
    int tx = threadIdx.x, ty0 = threadIdx.y;
    for (int ty = ty0; ty < 32; ty += 8)
        tile[ty][tx] = W[(size_t)p * INF_ * HD_ + (size_t)(k0 + ty) * HD_ + n0 + tx];
    __syncthreads();
    for (int ty = ty0; ty < 32; ty += 8) {
        float v = tile[tx][ty];
        __nv_bfloat16 hi = __float2bfloat16(v);
        size_t oi = (size_t)p * HD_ * INF_ + (size_t)(n0 + ty) * INF_ + k0 + tx;
        g_W_hi[oi] = hi;
        g_W_lo[oi] = __float2bfloat16(v - __bfloat162float(hi));
    }
}

// ---------------- mma / ldmatrix helpers ----------------
__device__ __forceinline__ void mma_bf16(float& c0, float& c1, float& c2, float& c3,
                                         uint32_t a0, uint32_t a1, uint32_t a2, uint32_t a3,
                                         uint32_t b0, uint32_t b1) {
    asm volatile("mma.sync.aligned.m16n8k16.row.col.f32.bf16.bf16.f32 "
                 "{%0,%1,%2,%3}, {%4,%5,%6,%7}, {%8,%9}, {%0,%1,%2,%3};"
                 : "+f"(c0), "+f"(c1), "+f"(c2), "+f"(c3)
                 : "r"(a0), "r"(a1), "r"(a2), "r"(a3), "r"(b0), "r"(b1));
}
__device__ __forceinline__ void ldsm4(uint32_t* r, const void* ptr) {
    uint32_t a = (uint32_t)__cvta_generic_to_shared(ptr);
    asm volatile("ldmatrix.sync.aligned.m8n8.x4.shared.b16 {%0,%1,%2,%3}, [%4];"
                 : "=r"(r[0]), "=r"(r[1]), "=r"(r[2]), "=r"(r[3]) : "r"(a));
}

// ---------------- K1: Wh = h @ W[p] (bf16 hi/lo 3-term) + fused el/er ----------------
// BM=64, BN=128, BK=32. 256 threads. grid: (157, 4, P)
__global__ __launch_bounds__(256) void k_gemm(const float* __restrict__ al,
                                              const float* __restrict__ ar) {
    __shared__ __nv_bfloat16 As_hi[64][40];
    __shared__ __nv_bfloat16 As_lo[64][40];
    __shared__ __nv_bfloat16 Bs_hi[128][40];
    __shared__ __nv_bfloat16 Bs_lo[128][40];
    __shared__ float s_att[64][2][2];

    int p  = blockIdx.z;
    int m0 = blockIdx.x * 64;
    int n0 = blockIdx.y * 128;
    int t    = threadIdx.x;
    int lane = t & 31;
    int w    = t >> 5;
    int warp_m = (w & 1) * 32;
    int warp_n = (w >> 1) * 32;
    int g   = lane >> 2;
    int tid = lane & 3;
    int lm_r = lane & 15;          // ldmatrix row within 16
    int lm_c = (lane >> 4) * 8;    // ldmatrix k-offset

    float acc[2][4][4];
    #pragma unroll
    for (int mt = 0; mt < 2; mt++)
        #pragma unroll
        for (int nt = 0; nt < 4; nt++)
            #pragma unroll
            for (int q = 0; q < 4; q++) acc[mt][nt][q] = 0.f;

    int a_row  = t >> 2;
    int a_koff = (t & 3) * 8;
    const __nv_bfloat16* ah_base  = &g_h_hi[(size_t)(m0 + a_row) * INF_ + a_koff];
    const __nv_bfloat16* alo_base = &g_h_lo[(size_t)(m0 + a_row) * INF_ + a_koff];
    int b_n0 = t >> 2;
    int b_k0 = (t & 3) * 8;
    int b_n1 = (t + 256) >> 2;
    int b_k1 = ((t + 256) & 3) * 8;
    const __nv_bfloat16* bW  = &g_W_hi[(size_t)p * HD_ * INF_ + (size_t)n0 * INF_];
    const __nv_bfloat16* bWl = &g_W_lo[(size_t)p * HD_ * INF_ + (size_t)n0 * INF_];

    uint4 pa_hi, pa_lo, pb_hi0, pb_hi1, pb_lo0, pb_lo1;
    pa_hi  = *(const uint4*)&ah_base[0];
    pa_lo  = *(const uint4*)&alo_base[0];
    pb_hi0 = *(const uint4*)&bW [(size_t)b_n0 * INF_ + b_k0];
    pb_hi1 = *(const uint4*)&bW [(size_t)b_n1 * INF_ + b_k1];
    pb_lo0 = *(const uint4*)&bWl[(size_t)b_n0 * INF_ + b_k0];
    pb_lo1 = *(const uint4*)&bWl[(size_t)b_n1 * INF_ + b_k1];

    for (int kb = 0; kb < 8; kb++) {
        __syncthreads();
        *(uint4*)&As_hi[a_row][a_koff] = pa_hi;
        *(uint4*)&As_lo[a_row][a_koff] = pa_lo;
        *(uint4*)&Bs_hi[b_n0][b_k0]    = pb_hi0;
        *(uint4*)&Bs_hi[b_n1][b_k1]    = pb_hi1;
        *(uint4*)&Bs_lo[b_n0][b_k0]    = pb_lo0;
        *(uint4*)&Bs_lo[b_n1][b_k1]    = pb_lo1;
        __syncthreads();
        if (kb < 7) {
            int kk = (kb + 1) * 32;
            pa_hi  = *(const uint4*)&ah_base[kk];
            pa_lo  = *(const uint4*)&alo_base[kk];
            pb_hi0 = *(const uint4*)&bW [(size_t)b_n0 * INF_ + kk + b_k0];
            pb_hi1 = *(const uint4*)&bW [(size_t)b_n1 * INF_ + kk + b_k1];
            pb_lo0 = *(const uint4*)&bWl[(size_t)b_n0 * INF_ + kk + b_k0];
            pb_lo1 = *(const uint4*)&bWl[(size_t)b_n1 * INF_ + kk + b_k1];
        }
        #pragma unroll
        for (int ks = 0; ks < 32; ks += 16) {
            uint32_t ah[2][4], al2[2][4], bh[2][4], bl2[2][4];
            #pragma unroll
            for (int mt = 0; mt < 2; mt++) {
                ldsm4(ah[mt],  &As_hi[warp_m + mt * 16 + lm_r][ks + lm_c]);
                ldsm4(al2[mt], &As_lo[warp_m + mt * 16 + lm_r][ks + lm_c]);
            }
            #pragma unroll
            for (int pr = 0; pr < 2; pr++) {
                ldsm4(bh[pr],  &Bs_hi[warp_n + pr * 16 + lm_r][ks + lm_c]);
                ldsm4(bl2[pr], &Bs_lo[warp_n + pr * 16 + lm_r][ks + lm_c]);
            }
            #pragma unroll
            for (int mt = 0; mt < 2; mt++)
                #pragma unroll
                for (int nt = 0; nt < 4; nt++) {
                    int pr = nt >> 1, o = nt & 1;
                    float* c = acc[mt][nt];
                    mma_bf16(c[0], c[1], c[2], c[3],
                             ah[mt][0], ah[mt][1], ah[mt][2], ah[mt][3],
                             bh[pr][o], bh[pr][o + 2]);
                    mma_bf16(c[0], c[1], c[2], c[3],
                             ah[mt][0], ah[mt][1], ah[mt][2], ah[mt][3],
                             bl2[pr][o], bl2[pr][o + 2]);
                    mma_bf16(c[0], c[1], c[2], c[3],
                             al2[mt][0], al2[mt][1], al2[mt][2], al2[mt][3],
                             bh[pr][o], bh[pr][o + 2]);
                }
        }
    }

    // ---- store Wh ----
    #pragma unroll
    for (int mt = 0; mt < 2; mt++) {
        int r0 = m0 + warp_m + mt * 16 + g;
        int r1 = r0 + 8;
        #pragma unroll
        for (int nt = 0; nt < 4; nt++) {
            int c = n0 + warp_n + nt * 8 + tid * 2;
            if (r0 < NN)
                *(float2*)&g_Wh[((size_t)p * NN + r0) * HD_ + c] =
                    make_float2(acc[mt][nt][0], acc[mt][nt][1]);
            if (r1 < NN)
                *(float2*)&g_Wh[((size_t)p * NN + r1) * HD_ + c] =
                    make_float2(acc[mt][nt][2], acc[mt][nt][3]);
        }
    }

    // ---- fused attention dot-products ----
    int head0 = n0 >> 6;
    int hw = warp_n >= 64;
    int dbase = (warp_n & 32);
    const float* alp = &al[((size_t)p * HH + head0 + hw) * DD];
    const float* arp = &ar[((size_t)p * HH + head0 + hw) * DD];

    s_att[t >> 2][(t >> 1) & 1][t & 1] = 0.f;
    __syncthreads();

    #pragma unroll
    for (int mt = 0; mt < 2; mt++) {
        #pragma unroll
        for (int rr = 0; rr < 2; rr++) {
            float pel = 0.f, per_ = 0.f;
            #pragma unroll
            for (int nt = 0; nt < 4; nt++) {
                #pragma unroll
                for (int j = 0; j < 2; j++) {
                    float c = acc[mt][nt][rr * 2 + j];
                    int dd = dbase + nt * 8 + tid * 2 + j;
                    pel  += c * alp[dd];
                    per_ += c * arp[dd];
                }
            }
            pel  += __shfl_xor_sync(~0u, pel, 1);  pel  += __shfl_xor_sync(~0u, pel, 2);
            per_ += __shfl_xor_sync(~0u, per_, 1); per_ += __shfl_xor_sync(~0u, per_, 2);
            if (tid == 0) {
                int row = warp_m + mt * 16 + g + rr * 8;
                atomicAdd(&s_att[row][hw][0], pel);
                atomicAdd(&s_att[row][hw][1], per_);
            }
        }
    }
    __syncthreads();
    {
        int row = t >> 2, h2 = (t >> 1) & 1, lr = t & 1;
        int gr = m0 + row;
        if (gr < NN) {
            float v = s_att[row][h2][lr];
            size_t idx = ((size_t)p * NN + gr) * HH + head0 + h2;
            if (lr == 0) g_el[idx] = v; else g_er[idx] = v;
        }
    }
}

// ---------------- CSR build ----------------
__global__ void k_count(const int* __restrict__ edst) {
    int e = blockIdx.x * blockDim.x + threadIdx.x;
    int p = blockIdx.y;
    atomicAdd(&g_cnt[p * NN + edst[(size_t)p * EE + e]], 1);
}

__global__ __launch_bounds__(1024) void k_scan() {
    __shared__ int part[1024];
    int p = blockIdx.x;
    int t = threadIdx.x;
    const int CH = 10;
    int b = t * CH;
    int loc[CH];
    int sum = 0;
    #pragma unroll
    for (int i = 0; i < CH; i++) {
        int idx = b + i;
        int v = (idx < NN) ? g_cnt[p * NN + idx] : 0;
        loc[i] = sum;
        sum += v;
    }
    part[t] = sum;
    __syncthreads();
    for (int ofs = 1; ofs < 1024; ofs <<= 1) {
        int val = (t >= ofs) ? part[t - ofs] : 0;
        __syncthreads();
        part[t] += val;
        __syncthreads();
    }
    int ex = part[t] - sum;
    #pragma unroll
    for (int i = 0; i < CH; i++) {
        int idx = b + i;
        if (idx < NN) {
            int o = ex + loc[i];
            g_off[p * NN + idx] = o;
            g_pos[p * NN + idx] = o;
        }
    }
}

__global__ void k_scatter(const int* __restrict__ esrc, const int* __restrict__ edst) {
    int e = blockIdx.x * blockDim.x + threadIdx.x;
    int p = blockIdx.y;
    int d = edst[(size_t)p * EE + e];
    int s = esrc[(size_t)p * EE + e];
    int pos = atomicAdd(&g_pos[p * NN + d], 1);
    g_sperm[(size_t)p * EE + pos] = s;
    g_dperm[(size_t)p * EE + pos] = d;
}

// ---------------- K3: exp(leakyrelu(el[s]+er[d])) in CSR order ----------------
__global__ void k_edgeA() {
    int i = blockIdx.x * blockDim.x + threadIdx.x;
    int p = blockIdx.y;
    int s = g_sperm[(size_t)p * EE + i];
    int d = g_dperm[(size_t)p * EE + i];
    const float4* el4 = (const float4*)&g_el[((size_t)p * NN + s) * HH];
    const float4* er4 = (const float4*)&g_er[((size_t)p * NN + d) * HH];
    float4*       ex4 = (float4*)&g_exp[((size_t)p * EE + i) * HH];
    #pragma unroll
    for (int q = 0; q < 2; q++) {
        float4 l = el4[q], r = er4[q];
        float v[4] = {l.x + r.x, l.y + r.y, l.z + r.z, l.w + r.w};
        float x[4];
        #pragma unroll
        for (int j = 0; j < 4; j++) {
            float vv = v[j] > 0.f ? v[j] : NEG_SLOPE * v[j];
            x[j] = expf(vv);
        }
        ex4[q] = make_float4(x[0], x[1], x[2], x[3]);
    }
}

// ---------------- K4: gather (4-edge unrolled, loads batched before FMAs) ----------
__global__ __launch_bounds__(256) void k_gather(const float* __restrict__ gb) {
    int lane = threadIdx.x & 31;
    int d = blockIdx.x * 8 + (threadIdx.x >> 5);
    int p = blockIdx.y;
    int head = lane >> 2;

    int start = g_off[p * NN + d];
    int deg   = g_cnt[p * NN + d];
    const int*   sp = &g_sperm[(size_t)p * EE + start];
    const float* xp = &g_exp[((size_t)p * EE + start) * HH + head];
    const float* whb = &g_Wh[(size_t)p * NN * HD_ + lane * 16];

    float acc[16];
    #pragma unroll
    for (int q = 0; q < 16; q++) acc[q] = 0.f;
    float ssum = 0.f;

    int j = 0;
    for (; j + 3 < deg; j += 4) {
        int s0 = sp[j], s1 = sp[j + 1], s2 = sp[j + 2], s3 = sp[j + 3];
        float x0 = xp[(size_t)j * HH];
        float x1 = xp[(size_t)(j + 1) * HH];
        float x2 = xp[(size_t)(j + 2) * HH];
        float x3 = xp[(size_t)(j + 3) * HH];
        const float4* A = (const float4*)&whb[(size_t)s0 * HD_];
        const float4* B = (const float4*)&whb[(size_t)s1 * HD_];
        const float4* C = (const float4*)&whb[(size_t)s2 * HD_];
        const float4* D = (const float4*)&whb[(size_t)s3 * HD_];
        float4 a0 = A[0], a1 = A[1], a2 = A[2], a3 = A[3];
        float4 b0 = B[0], b1 = B[1], b2 = B[2], b3 = B[3];
        float4 c0 = C[0], c1 = C[1], c2 = C[2], c3 = C[3];
        float4 d0 = D[0], d1 = D[1], d2 = D[2], d3 = D[3];
        ssum += x0 + x1 + x2 + x3;
        acc[0]  += x0*a0.x + x1*b0.x + x2*c0.x + x3*d0.x;
        acc[1]  += x0*a0.y + x1*b0.y + x2*c0.y + x3*d0.y;
        acc[2]  += x0*a0.z + x1*b0.z + x2*c0.z + x3*d0.z;
        acc[3]  += x0*a0.w + x1*b0.w + x2*c0.w + x3*d0.w;
        acc[4]  += x0*a1.x + x1*b1.x + x2*c1.x + x3*d1.x;
        acc[5]  += x0*a1.y + x1*b1.y + x2*c1.y + x3*d1.y;
        acc[6]  += x0*a1.z + x1*b1.z + x2*c1.z + x3*d1.z;
        acc[7]  += x0*a1.w + x1*b1.w + x2*c1.w + x3*d1.w;
        acc[8]  += x0*a2.x + x1*b2.x + x2*c2.x + x3*d2.x;
        acc[9]  += x0*a2.y + x1*b2.y + x2*c2.y + x3*d2.y;
        acc[10] += x0*a2.z + x1*b2.z + x2*c2.z + x3*d2.z;
        acc[11] += x0*a2.w + x1*b2.w + x2*c2.w + x3*d2.w;
        acc[12] += x0*a3.x + x1*b3.x + x2*c3.x + x3*d3.x;
        acc[13] += x0*a3.y + x1*b3.y + x2*c3.y + x3*d3.y;
        acc[14] += x0*a3.z + x1*b3.z + x2*c3.z + x3*d3.z;
        acc[15] += x0*a3.w + x1*b3.w + x2*c3.w + x3*d3.w;
    }
    for (; j < deg; j++) {
        int s0 = sp[j];
        float xv = xp[(size_t)j * HH];
        const float4* A = (const float4*)&whb[(size_t)s0 * HD_];
        ssum += xv;
        #pragma unroll
        for (int q = 0; q < 4; q++) {
            float4 v = A[q];
            acc[4 * q + 0] += xv * v.x;  acc[4 * q + 1] += xv * v.y;
            acc[4 * q + 2] += xv * v.z;  acc[4 * q + 3] += xv * v.w;
        }
    }

    float inv = (ssum > 0.f) ? 1.f / ssum : 0.f;
    float* dst = &g_z[((size_t)p * NN + d) * HD_ + lane * 16];
    const float* bp = &gb[p * HD_ + lane * 16];
    #pragma unroll
    for (int q = 0; q < 4; q++) {
        float4 b4 = *(const float4*)&bp[q * 4];
        float o[4];
        o[0] = acc[4 * q + 0] * inv + b4.x;
        o[1] = acc[4 * q + 1] * inv + b4.y;
        o[2] = acc[4 * q + 2] * inv + b4.z;
        o[3] = acc[4 * q + 3] * inv + b4.w;
        #pragma unroll
        for (int jj = 0; jj < 4; jj++) o[jj] = o[jj] > 0.f ? o[jj] : expm1f(o[jj]);
        *(float4*)&dst[q * 4] = make_float4(o[0], o[1], o[2], o[3]);
    }
}

// ---------------- K5: semantic partial, 32 nodes/block, dynamic smem ----------------
#define POST_NB 32
#define POST_SMEM ((POST_NB * HD_ + 64 * 64 + 256) * sizeof(float))
__global__ __launch_bounds__(256) void k_post(const float* __restrict__ W1,
                                              const float* __restrict__ b1,
                                              const float* __restrict__ W2) {
    extern __shared__ float dsm[];
    float* zs  = dsm;                     // 32*512
    float* w1s = dsm + POST_NB * HD_;     // 64*64
    float* red = w1s + 64 * 64;           // 256
    int p  = blockIdx.y;
    int n0 = blockIdx.x * POST_NB;
    int t  = threadIdx.x;
    for (int i = t; i < POST_NB * HD_; i += 256) {
        int node = i >> 9, c = i & 511;
        int gn = n0 + node;
        zs[i] = (gn < NN) ? g_z[((size_t)p * NN + gn) * HD_ + c] : 0.f;
    }
    __syncthreads();
    int j = t & 63, grp = t >> 6;         // 8 nodes per thread
    float acc[8];
    #pragma unroll
    for (int u = 0; u < 8; u++) acc[u] = 0.f;
    for (int kc = 0; kc < 8; kc++) {
        for (int i = t; i < 64 * 64; i += 256)
            w1s[i] = W1[(size_t)(kc * 64 + (i >> 6)) * 64 + (i & 63)];
        __syncthreads();
        #pragma unroll 16
        for (int k = 0; k < 64; k++) {
            float w1 = w1s[k * 64 + j];
            int zb = kc * 64 + k;
            #pragma unroll
            for (int u = 0; u < 8; u++)
                acc[u] += zs[(grp * 8 + u) * HD_ + zb] * w1;
        }
        __syncthreads();
    }
    float b = b1[j], w2 = W2[j];
    float contrib = 0.f;
    #pragma unroll
    for (int u = 0; u < 8; u++) {
        int gn = n0 + grp * 8 + u;
        if (gn < NN) contrib += tanhf(acc[u] + b) * w2;
    }
    red[t] = contrib;
    __syncthreads();
    for (int ofs = 128; ofs > 0; ofs >>= 1) {
        if (t < ofs) red[t] += red[t + ofs];
        __syncthreads();
    }
    if (t == 0) atomicAdd(&g_w[p], red[0]);
}

// ---------------- K6: beta ----------------
__global__ void k_beta() {
    if (threadIdx.x == 0) {
        float w[PP], m = -1e30f;
        #pragma unroll
        for (int p = 0; p < PP; p++) { w[p] = g_w[p] / (float)NN; m = fmaxf(m, w[p]); }
        float s = 0.f;
        #pragma unroll
        for (int p = 0; p < PP; p++) { w[p] = expf(w[p] - m); s += w[p]; }
        #pragma unroll
        for (int p = 0; p < PP; p++) g_beta[p] = w[p] / s;
    }
}

// ---------------- K7: combine ----------------
__global__ void k_comb(float* __restrict__ out) {
    int i = blockIdx.x * blockDim.x + threadIdx.x;
    const float4* z = (const float4*)g_z;
    const size_t stride = (size_t)NN * HD_ / 4;
    float b0 = g_beta[0], b1 = g_beta[1], b2 = g_beta[2], b3 = g_beta[3];
    float4 a = z[i];
    float4 b = z[i + stride];
    float4 c = z[i + 2 * stride];
    float4 d = z[i + 3 * stride];
    float4 o;
    o.x = b0 * a.x + b1 * b.x + b2 * c.x + b3 * d.x;
    o.y = b0 * a.y + b1 * b.y + b2 * c.y + b3 * d.y;
    o.z = b0 * a.z + b1 * b.z + b2 * c.z + b3 * d.z;
    o.w = b0 * a.w + b1 * b.w + b2 * c.w + b3 * d.w;
    ((float4*)out)[i] = o;
}

// ---------------- launcher ----------------
extern "C" void kernel_launch(void* const* d_in, const int* in_sizes, int n_in,
                              void* d_out, int out_size) {
    const float* h     = (const float*)d_in[0];
    const int*   esrc  = (const int*)  d_in[1];
    const int*   edst  = (const int*)  d_in[2];
    const float* gat_W = (const float*)d_in[3];
    const float* al    = (const float*)d_in[4];
    const float* ar    = (const float*)d_in[5];
    const float* gat_b = (const float*)d_in[6];
    const float* sW1   = (const float*)d_in[7];
    const float* sb1   = (const float*)d_in[8];
    const float* sW2   = (const float*)d_in[9];
    float* out = (float*)d_out;

    static bool attr_done = false;
    if (!attr_done) {
        cudaFuncSetAttribute(k_post, cudaFuncAttributeMaxDynamicSharedMemorySize,
                             (int)POST_SMEM);
        attr_done = true;
    }

    // order chosen so k_gemm is launch #4 (ncu captures launch #4)
    k_zero<<<(PP * NN + 255) / 256, 256>>>();
    k_cvt_h<<<(NN * INF_ + 255) / 256, 256>>>(h);
    dim3 gw(INF_ / 32, HD_ / 32, PP);
    k_cvt_W<<<gw, dim3(32, 8)>>>(gat_W);

    dim3 gg((NN + 63) / 64, HD_ / 128, PP);
    k_gemm<<<gg, 256>>>(al, ar);

    dim3 ge(EE / 256, PP);
    k_count<<<ge, 256>>>(edst);
    k_scan<<<PP, 1024>>>();
    k_scatter<<<ge, 256>>>(esrc, edst);

    k_edgeA<<<ge, 256>>>();

    dim3 gga((NN + 7) / 8, PP);
    k_gather<<<gga, 256>>>(gat_b);

    dim3 gp((NN + POST_NB - 1) / POST_NB, PP);
    k_post<<<gp, 256, POST_SMEM>>>(sW1, sb1, sW2);

    k_beta<<<1, 32>>>();

    k_comb<<<(NN * HD_ / 4) / 256, 256>>>(out);
}

// round 9
// speedup vs baseline: 2.3322x; 1.2158x over previous
#include <cuda_runtime.h>
#include <cuda_bf16.h>
#include <cuda_fp16.h>
#include <cstdint>

#define NN   10000
#define NPAD 10048          // 157*64
#define PP   4
#define EE   160000
#define INF_ 256
#define HH   8
#define DD   64
#define HD_  512
#define NEG_SLOPE 0.2f

// ---------------- device scratch ----------------
__device__ __half g_Whh[(size_t)PP * NN * HD_];   // fp16 Wh (gather input)
__device__ float g_z [(size_t)PP * NN * HD_];
__device__ float g_el[(size_t)PP * NN * HH];
__device__ float g_er[(size_t)PP * NN * HH];
__device__ float g_exp[(size_t)PP * EE * HH];     // exp(leakyrelu), CSR order
__device__ int   g_cnt[PP * NN];
__device__ int   g_off[PP * NN];
__device__ int   g_pos[PP * NN];
__device__ int   g_sperm[(size_t)PP * EE];
__device__ int   g_dperm[(size_t)PP * EE];
__device__ __nv_bfloat16 g_h_hi[(size_t)NPAD * INF_];   // pad rows stay zero
__device__ __nv_bfloat16 g_h_lo[(size_t)NPAD * INF_];
__device__ __nv_bfloat16 g_W_hi[(size_t)PP * HD_ * INF_];  // [p][n][k]
__device__ __nv_bfloat16 g_W_lo[(size_t)PP * HD_ * INF_];
__device__ float g_w [PP];
__device__ float g_beta[PP];

// ---------------- K0 ----------------
__global__ void k_zero() {
    int i = blockIdx.x * blockDim.x + threadIdx.x;
    if (i < PP * NN) g_cnt[i] = 0;
    if (i < PP) g_w[i] = 0.f;
}

// ---------------- convert h to bf16 hi/lo ----------------
__global__ void k_cvt_h(const float* __restrict__ h) {
    int i = blockIdx.x * blockDim.x + threadIdx.x;
    if (i < NN * INF_) {
        float v = h[i];
        __nv_bfloat16 hi = __float2bfloat16(v);
        g_h_hi[i] = hi;
        g_h_lo[i] = __float2bfloat16(v - __bfloat162float(hi));
    }
}

// ---------------- convert + transpose W ----------------
__global__ void k_cvt_W(const float* __restrict__ W) {
    __shared__ float tile[32][33];
    int p  = blockIdx.z;
    int k0 = blockIdx.x * 32;
    int n0 = blockIdx.y * 32;
    int tx = threadIdx.x, ty0 = threadIdx.y;
    for (int ty = ty0; ty < 32; ty += 8)
        tile[ty][tx] = W[(size_t)p * INF_ * HD_ + (size_t)(k0 + ty) * HD_ + n0 + tx];
    __syncthreads();
    for (int ty = ty0; ty < 32; ty += 8) {
        float v = tile[tx][ty];
        __nv_bfloat16 hi = __float2bfloat16(v);
        size_t oi = (size_t)p * HD_ * INF_ + (size_t)(n0 + ty) * INF_ + k0 + tx;
        g_W_hi[oi] = hi;
        g_W_lo[oi] = __float2bfloat16(v - __bfloat162float(hi));
    }
}

// ---------------- mma / ldmatrix helpers ----------------
__device__ __forceinline__ void mma_bf16(float& c0, float& c1, float& c2, float& c3,
                                         uint32_t a0, uint32_t a1, uint32_t a2, uint32_t a3,
                                         uint32_t b0, uint32_t b1) {
    asm volatile("mma.sync.aligned.m16n8k16.row.col.f32.bf16.bf16.f32 "
                 "{%0,%1,%2,%3}, {%4,%5,%6,%7}, {%8,%9}, {%0,%1,%2,%3};"
                 : "+f"(c0), "+f"(c1), "+f"(c2), "+f"(c3)
                 : "r"(a0), "r"(a1), "r"(a2), "r"(a3), "r"(b0), "r"(b1));
}
__device__ __forceinline__ void ldsm4(uint32_t* r, const void* ptr) {
    uint32_t a = (uint32_t)__cvta_generic_to_shared(ptr);
    asm volatile("ldmatrix.sync.aligned.m8n8.x4.shared.b16 {%0,%1,%2,%3}, [%4];"
                 : "=r"(r[0]), "=r"(r[1]), "=r"(r[2]), "=r"(r[3]) : "r"(a));
}

// ---------------- K1: Wh = h @ W[p] (bf16 hi/lo 3-term) + fused el/er ----------------
// BM=64, BN=128, BK=32. 256 threads. grid: (157, 4, P)
__global__ __launch_bounds__(256) void k_gemm(const float* __restrict__ al,
                                              const float* __restrict__ ar) {
    __shared__ __nv_bfloat16 As_hi[64][40];
    __shared__ __nv_bfloat16 As_lo[64][40];
    __shared__ __nv_bfloat16 Bs_hi[128][40];
    __shared__ __nv_bfloat16 Bs_lo[128][40];
    __shared__ float s_att[64][2][2];

    int p  = blockIdx.z;
    int m0 = blockIdx.x * 64;
    int n0 = blockIdx.y * 128;
    int t    = threadIdx.x;
    int lane = t & 31;
    int w    = t >> 5;
    int warp_m = (w & 1) * 32;
    int warp_n = (w >> 1) * 32;
    int g   = lane >> 2;
    int tid = lane & 3;
    int lm_r = lane & 15;
    int lm_c = (lane >> 4) * 8;

    float acc[2][4][4];
    #pragma unroll
    for (int mt = 0; mt < 2; mt++)
        #pragma unroll
        for (int nt = 0; nt < 4; nt++)
            #pragma unroll
            for (int q = 0; q < 4; q++) acc[mt][nt][q] = 0.f;

    int a_row  = t >> 2;
    int a_koff = (t & 3) * 8;
    const __nv_bfloat16* ah_base  = &g_h_hi[(size_t)(m0 + a_row) * INF_ + a_koff];
    const __nv_bfloat16* alo_base = &g_h_lo[(size_t)(m0 + a_row) * INF_ + a_koff];
    int b_n0 = t >> 2;
    int b_k0 = (t & 3) * 8;
    int b_n1 = (t + 256) >> 2;
    int b_k1 = ((t + 256) & 3) * 8;
    const __nv_bfloat16* bW  = &g_W_hi[(size_t)p * HD_ * INF_ + (size_t)n0 * INF_];
    const __nv_bfloat16* bWl = &g_W_lo[(size_t)p * HD_ * INF_ + (size_t)n0 * INF_];

    uint4 pa_hi, pa_lo, pb_hi0, pb_hi1, pb_lo0, pb_lo1;
    pa_hi  = *(const uint4*)&ah_base[0];
    pa_lo  = *(const uint4*)&alo_base[0];
    pb_hi0 = *(const uint4*)&bW [(size_t)b_n0 * INF_ + b_k0];
    pb_hi1 = *(const uint4*)&bW [(size_t)b_n1 * INF_ + b_k1];
    pb_lo0 = *(const uint4*)&bWl[(size_t)b_n0 * INF_ + b_k0];
    pb_lo1 = *(const uint4*)&bWl[(size_t)b_n1 * INF_ + b_k1];

    for (int kb = 0; kb < 8; kb++) {
        __syncthreads();
        *(uint4*)&As_hi[a_row][a_koff] = pa_hi;
        *(uint4*)&As_lo[a_row][a_koff] = pa_lo;
        *(uint4*)&Bs_hi[b_n0][b_k0]    = pb_hi0;
        *(uint4*)&Bs_hi[b_n1][b_k1]    = pb_hi1;
        *(uint4*)&Bs_lo[b_n0][b_k0]    = pb_lo0;
        *(uint4*)&Bs_lo[b_n1][b_k1]    = pb_lo1;
        __syncthreads();
        if (kb < 7) {
            int kk = (kb + 1) * 32;
            pa_hi  = *(const uint4*)&ah_base[kk];
            pa_lo  = *(const uint4*)&alo_base[kk];
            pb_hi0 = *(const uint4*)&bW [(size_t)b_n0 * INF_ + kk + b_k0];
            pb_hi1 = *(const uint4*)&bW [(size_t)b_n1 * INF_ + kk + b_k1];
            pb_lo0 = *(const uint4*)&bWl[(size_t)b_n0 * INF_ + kk + b_k0];
            pb_lo1 = *(const uint4*)&bWl[(size_t)b_n1 * INF_ + kk + b_k1];
        }
        #pragma unroll
        for (int ks = 0; ks < 32; ks += 16) {
            uint32_t ah[2][4], al2[2][4], bh[2][4], bl2[2][4];
            #pragma unroll
            for (int mt = 0; mt < 2; mt++) {
                ldsm4(ah[mt],  &As_hi[warp_m + mt * 16 + lm_r][ks + lm_c]);
                ldsm4(al2[mt], &As_lo[warp_m + mt * 16 + lm_r][ks + lm_c]);
            }
            #pragma unroll
            for (int pr = 0; pr < 2; pr++) {
                ldsm4(bh[pr],  &Bs_hi[warp_n + pr * 16 + lm_r][ks + lm_c]);
                ldsm4(bl2[pr], &Bs_lo[warp_n + pr * 16 + lm_r][ks + lm_c]);
            }
            #pragma unroll
            for (int mt = 0; mt < 2; mt++)
                #pragma unroll
                for (int nt = 0; nt < 4; nt++) {
                    int pr = nt >> 1, o = nt & 1;
                    float* c = acc[mt][nt];
                    mma_bf16(c[0], c[1], c[2], c[3],
                             ah[mt][0], ah[mt][1], ah[mt][2], ah[mt][3],
                             bh[pr][o], bh[pr][o + 2]);
                    mma_bf16(c[0], c[1], c[2], c[3],
                             ah[mt][0], ah[mt][1], ah[mt][2], ah[mt][3],
                             bl2[pr][o], bl2[pr][o + 2]);
                    mma_bf16(c[0], c[1], c[2], c[3],
                             al2[mt][0], al2[mt][1], al2[mt][2], al2[mt][3],
                             bh[pr][o], bh[pr][o + 2]);
                }
        }
    }

    // ---- store Wh as fp16 ----
    #pragma unroll
    for (int mt = 0; mt < 2; mt++) {
        int r0 = m0 + warp_m + mt * 16 + g;
        int r1 = r0 + 8;
        #pragma unroll
        for (int nt = 0; nt < 4; nt++) {
            int c = n0 + warp_n + nt * 8 + tid * 2;
            if (r0 < NN)
                *(__half2*)&g_Whh[((size_t)p * NN + r0) * HD_ + c] =
                    __floats2half2_rn(acc[mt][nt][0], acc[mt][nt][1]);
            if (r1 < NN)
                *(__half2*)&g_Whh[((size_t)p * NN + r1) * HD_ + c] =
                    __floats2half2_rn(acc[mt][nt][2], acc[mt][nt][3]);
        }
    }

    // ---- fused attention dot-products (fp32 accumulators) ----
    int head0 = n0 >> 6;
    int hw = warp_n >= 64;
    int dbase = (warp_n & 32);
    const float* alp = &al[((size_t)p * HH + head0 + hw) * DD];
    const float* arp = &ar[((size_t)p * HH + head0 + hw) * DD];

    s_att[t >> 2][(t >> 1) & 1][t & 1] = 0.f;
    __syncthreads();

    #pragma unroll
    for (int mt = 0; mt < 2; mt++) {
        #pragma unroll
        for (int rr = 0; rr < 2; rr++) {
            float pel = 0.f, per_ = 0.f;
            #pragma unroll
            for (int nt = 0; nt < 4; nt++) {
                #pragma unroll
                for (int j = 0; j < 2; j++) {
                    float c = acc[mt][nt][rr * 2 + j];
                    int dd = dbase + nt * 8 + tid * 2 + j;
                    pel  += c * alp[dd];
                    per_ += c * arp[dd];
                }
            }
            pel  += __shfl_xor_sync(~0u, pel, 1);  pel  += __shfl_xor_sync(~0u, pel, 2);
            per_ += __shfl_xor_sync(~0u, per_, 1); per_ += __shfl_xor_sync(~0u, per_, 2);
            if (tid == 0) {
                int row = warp_m + mt * 16 + g + rr * 8;
                atomicAdd(&s_att[row][hw][0], pel);
                atomicAdd(&s_att[row][hw][1], per_);
            }
        }
    }
    __syncthreads();
    {
        int row = t >> 2, h2 = (t >> 1) & 1, lr = t & 1;
        int gr = m0 + row;
        if (gr < NN) {
            float v = s_att[row][h2][lr];
            size_t idx = ((size_t)p * NN + gr) * HH + head0 + h2;
            if (lr == 0) g_el[idx] = v; else g_er[idx] = v;
        }
    }
}

// ---------------- CSR build ----------------
__global__ void k_count(const int* __restrict__ edst) {
    int e = blockIdx.x * blockDim.x + threadIdx.x;
    int p = blockIdx.y;
    atomicAdd(&g_cnt[p * NN + edst[(size_t)p * EE + e]], 1);
}

__global__ __launch_bounds__(1024) void k_scan() {
    __shared__ int part[1024];
    int p = blockIdx.x;
    int t = threadIdx.x;
    const int CH = 10;
    int b = t * CH;
    int loc[CH];
    int sum = 0;
    #pragma unroll
    for (int i = 0; i < CH; i++) {
        int idx = b + i;
        int v = (idx < NN) ? g_cnt[p * NN + idx] : 0;
        loc[i] = sum;
        sum += v;
    }
    part[t] = sum;
    __syncthreads();
    for (int ofs = 1; ofs < 1024; ofs <<= 1) {
        int val = (t >= ofs) ? part[t - ofs] : 0;
        __syncthreads();
        part[t] += val;
        __syncthreads();
    }
    int ex = part[t] - sum;
    #pragma unroll
    for (int i = 0; i < CH; i++) {
        int idx = b + i;
        if (idx < NN) {
            int o = ex + loc[i];
            g_off[p * NN + idx] = o;
            g_pos[p * NN + idx] = o;
        }
    }
}

__global__ void k_scatter(const int* __restrict__ esrc, const int* __restrict__ edst) {
    int e = blockIdx.x * blockDim.x + threadIdx.x;
    int p = blockIdx.y;
    int d = edst[(size_t)p * EE + e];
    int s = esrc[(size_t)p * EE + e];
    int pos = atomicAdd(&g_pos[p * NN + d], 1);
    g_sperm[(size_t)p * EE + pos] = s;
    g_dperm[(size_t)p * EE + pos] = d;
}

// ---------------- K3: exp(leakyrelu(el[s]+er[d])) in CSR order ----------------
__global__ void k_edgeA() {
    int i = blockIdx.x * blockDim.x + threadIdx.x;
    int p = blockIdx.y;
    int s = g_sperm[(size_t)p * EE + i];
    int d = g_dperm[(size_t)p * EE + i];
    const float4* el4 = (const float4*)&g_el[((size_t)p * NN + s) * HH];
    const float4* er4 = (const float4*)&g_er[((size_t)p * NN + d) * HH];
    float4*       ex4 = (float4*)&g_exp[((size_t)p * EE + i) * HH];
    #pragma unroll
    for (int q = 0; q < 2; q++) {
        float4 l = el4[q], r = er4[q];
        float v[4] = {l.x + r.x, l.y + r.y, l.z + r.z, l.w + r.w};
        float x[4];
        #pragma unroll
        for (int j = 0; j < 4; j++) {
            float vv = v[j] > 0.f ? v[j] : NEG_SLOPE * v[j];
            x[j] = expf(vv);
        }
        ex4[q] = make_float4(x[0], x[1], x[2], x[3]);
    }
}

// ---------------- K4: gather from fp16 Wh ----------------
__device__ __forceinline__ void acc_h8(float* acc, uint4 u, float xv) {
    float2 f0 = __half22float2(*(__half2*)&u.x);
    float2 f1 = __half22float2(*(__half2*)&u.y);
    float2 f2 = __half22float2(*(__half2*)&u.z);
    float2 f3 = __half22float2(*(__half2*)&u.w);
    acc[0] += xv * f0.x;  acc[1] += xv * f0.y;
    acc[2] += xv * f1.x;  acc[3] += xv * f1.y;
    acc[4] += xv * f2.x;  acc[5] += xv * f2.y;
    acc[6] += xv * f3.x;  acc[7] += xv * f3.y;
}

__global__ __launch_bounds__(256) void k_gather(const float* __restrict__ gb) {
    int lane = threadIdx.x & 31;
    int d = blockIdx.x * 8 + (threadIdx.x >> 5);
    int p = blockIdx.y;
    int head = lane >> 2;

    int start = g_off[p * NN + d];
    int deg   = g_cnt[p * NN + d];
    const int*    sp  = &g_sperm[(size_t)p * EE + start];
    const float*  xp  = &g_exp[((size_t)p * EE + start) * HH + head];
    const __half* whb = &g_Whh[(size_t)p * NN * HD_ + lane * 16];

    float acc[16];
    #pragma unroll
    for (int q = 0; q < 16; q++) acc[q] = 0.f;
    float ssum = 0.f;

    int j = 0;
    for (; j + 3 < deg; j += 4) {
        int s0 = sp[j], s1 = sp[j + 1], s2 = sp[j + 2], s3 = sp[j + 3];
        float x0 = xp[(size_t)j * HH];
        float x1 = xp[(size_t)(j + 1) * HH];
        float x2 = xp[(size_t)(j + 2) * HH];
        float x3 = xp[(size_t)(j + 3) * HH];
        const uint4* A = (const uint4*)&whb[(size_t)s0 * HD_];
        const uint4* B = (const uint4*)&whb[(size_t)s1 * HD_];
        const uint4* C = (const uint4*)&whb[(size_t)s2 * HD_];
        const uint4* D = (const uint4*)&whb[(size_t)s3 * HD_];
        uint4 a0 = A[0], a1 = A[1];
        uint4 b0 = B[0], b1 = B[1];
        uint4 c0 = C[0], c1 = C[1];
        uint4 d0 = D[0], d1 = D[1];
        ssum += x0 + x1 + x2 + x3;
        acc_h8(acc,     a0, x0);  acc_h8(acc + 8, a1, x0);
        acc_h8(acc,     b0, x1);  acc_h8(acc + 8, b1, x1);
        acc_h8(acc,     c0, x2);  acc_h8(acc + 8, c1, x2);
        acc_h8(acc,     d0, x3);  acc_h8(acc + 8, d1, x3);
    }
    for (; j < deg; j++) {
        int s0 = sp[j];
        float xv = xp[(size_t)j * HH];
        const uint4* A = (const uint4*)&whb[(size_t)s0 * HD_];
        uint4 a0 = A[0], a1 = A[1];
        ssum += xv;
        acc_h8(acc, a0, xv);  acc_h8(acc + 8, a1, xv);
    }

    float inv = (ssum > 0.f) ? 1.f / ssum : 0.f;
    float* dst = &g_z[((size_t)p * NN + d) * HD_ + lane * 16];
    const float* bp = &gb[p * HD_ + lane * 16];
    #pragma unroll
    for (int q = 0; q < 4; q++) {
        float4 b4 = *(const float4*)&bp[q * 4];
        float o[4];
        o[0] = acc[4 * q + 0] * inv + b4.x;
        o[1] = acc[4 * q + 1] * inv + b4.y;
        o[2] = acc[4 * q + 2] * inv + b4.z;
        o[3] = acc[4 * q + 3] * inv + b4.w;
        #pragma unroll
        for (int jj = 0; jj < 4; jj++) o[jj] = o[jj] > 0.f ? o[jj] : expm1f(o[jj]);
        *(float4*)&dst[q * 4] = make_float4(o[0], o[1], o[2], o[3]);
    }
}

// ---------------- K5: semantic partial ----------------
#define POST_NB 32
#define POST_SMEM ((POST_NB * HD_ + 64 * 64 + 256) * sizeof(float))
__global__ __launch_bounds__(256) void k_post(const float* __restrict__ W1,
                                              const float* __restrict__ b1,
                                              const float* __restrict__ W2) {
    extern __shared__ float dsm[];
    float* zs  = dsm;
    float* w1s = dsm + POST_NB * HD_;
    float* red = w1s + 64 * 64;
    int p  = blockIdx.y;
    int n0 = blockIdx.x * POST_NB;
    int t  = threadIdx.x;
    for (int i = t; i < POST_NB * HD_; i += 256) {
        int node = i >> 9, c = i & 511;
        int gn = n0 + node;
        zs[i] = (gn < NN) ? g_z[((size_t)p * NN + gn) * HD_ + c] : 0.f;
    }
    __syncthreads();
    int j = t & 63, grp = t >> 6;
    float acc[8];
    #pragma unroll
    for (int u = 0; u < 8; u++) acc[u] = 0.f;
    for (int kc = 0; kc < 8; kc++) {
        for (int i = t; i < 64 * 64; i += 256)
            w1s[i] = W1[(size_t)(kc * 64 + (i >> 6)) * 64 + (i & 63)];
        __syncthreads();
        #pragma unroll 16
        for (int k = 0; k < 64; k++) {
            float w1 = w1s[k * 64 + j];
            int zb = kc * 64 + k;
            #pragma unroll
            for (int u = 0; u < 8; u++)
                acc[u] += zs[(grp * 8 + u) * HD_ + zb] * w1;
        }
        __syncthreads();
    }
    float b = b1[j], w2 = W2[j];
    float contrib = 0.f;
    #pragma unroll
    for (int u = 0; u < 8; u++) {
        int gn = n0 + grp * 8 + u;
        if (gn < NN) contrib += tanhf(acc[u] + b) * w2;
    }
    red[t] = contrib;
    __syncthreads();
    for (int ofs = 128; ofs > 0; ofs >>= 1) {
        if (t < ofs) red[t] += red[t + ofs];
        __syncthreads();
    }
    if (t == 0) atomicAdd(&g_w[p], red[0]);
}

// ---------------- K6: beta ----------------
__global__ void k_beta() {
    if (threadIdx.x == 0) {
        float w[PP], m = -1e30f;
        #pragma unroll
        for (int p = 0; p < PP; p++) { w[p] = g_w[p] / (float)NN; m = fmaxf(m, w[p]); }
        float s = 0.f;
        #pragma unroll
        for (int p = 0; p < PP; p++) { w[p] = expf(w[p] - m); s += w[p]; }
        #pragma unroll
        for (int p = 0; p < PP; p++) g_beta[p] = w[p] / s;
    }
}

// ---------------- K7: combine ----------------
__global__ void k_comb(float* __restrict__ out) {
    int i = blockIdx.x * blockDim.x + threadIdx.x;
    const float4* z = (const float4*)g_z;
    const size_t stride = (size_t)NN * HD_ / 4;
    float b0 = g_beta[0], b1 = g_beta[1], b2 = g_beta[2], b3 = g_beta[3];
    float4 a = z[i];
    float4 b = z[i + stride];
    float4 c = z[i + 2 * stride];
    float4 d = z[i + 3 * stride];
    float4 o;
    o.x = b0 * a.x + b1 * b.x + b2 * c.x + b3 * d.x;
    o.y = b0 * a.y + b1 * b.y + b2 * c.y + b3 * d.y;
    o.z = b0 * a.z + b1 * b.z + b2 * c.z + b3 * d.z;
    o.w = b0 * a.w + b1 * b.w + b2 * c.w + b3 * d.w;
    ((float4*)out)[i] = o;
}

// ---------------- launcher ----------------
extern "C" void kernel_launch(void* const* d_in, const int* in_sizes, int n_in,
                              void* d_out, int out_size) {
    const float* h     = (const float*)d_in[0];
    const int*   esrc  = (const int*)  d_in[1];
    const int*   edst  = (const int*)  d_in[2];
    const float* gat_W = (const float*)d_in[3];
    const float* al    = (const float*)d_in[4];
    const float* ar    = (const float*)d_in[5];
    const float* gat_b = (const float*)d_in[6];
    const float* sW1   = (const float*)d_in[7];
    const float* sb1   = (const float*)d_in[8];
    const float* sW2   = (const float*)d_in[9];
    float* out = (float*)d_out;

    // idempotent, called every time (no static guards — determinism rule)
    cudaFuncSetAttribute(k_post, cudaFuncAttributeMaxDynamicSharedMemorySize,
                         (int)POST_SMEM);

    k_zero<<<(PP * NN + 255) / 256, 256>>>();
    k_cvt_h<<<(NN * INF_ + 255) / 256, 256>>>(h);
    dim3 gw(INF_ / 32, HD_ / 32, PP);
    k_cvt_W<<<gw, dim3(32, 8)>>>(gat_W);

    dim3 gg((NN + 63) / 64, HD_ / 128, PP);
    k_gemm<<<gg, 256>>>(al, ar);

    dim3 ge(EE / 256, PP);
    k_count<<<ge, 256>>>(edst);
    k_scan<<<PP, 1024>>>();
    k_scatter<<<ge, 256>>>(esrc, edst);

    k_edgeA<<<ge, 256>>>();

    dim3 gga((NN + 7) / 8, PP);
    k_gather<<<gga, 256>>>(gat_b);

    dim3 gp((NN + POST_NB - 1) / POST_NB, PP);
    k_post<<<gp, 256, POST_SMEM>>>(sW1, sb1, sW2);

    k_beta<<<1, 32>>>();

    k_comb<<<(NN * HD_ / 4) / 256, 256>>>(out);
}